// round 9
// baseline (speedup 1.0000x reference)
#include <cuda_runtime.h>
#include <cuda_bf16.h>
#include <cstdint>
#include <cstddef>

#define BB  128
#define SS  512
#define EE  128
#define HH  256
#define HD  512
#define TT  127

typedef unsigned long long ull;

// ------------------------- device scratch ------------------------------------
__device__ float g_xw_f[(size_t)SS*BB*4*HH];
__device__ float g_xw_b[(size_t)SS*BB*4*HH];
__device__ float g_h_enc[2][2][BB*HH];                 // [parity][dir]
__device__ float g_c_enc[2][BB*HH];                    // final cells [dir]
__device__ __nv_bfloat162 g_encout_bf[(size_t)BB*SS*256]; // (b,s,512) bf16
__device__ __nv_bfloat162 g_encproj[(size_t)BB*SS*256];   // bf16 + attn_b
__device__ float g_xg[(size_t)TT*BB*4*HD];
__device__ float g_wcat[(size_t)4*HD*1024];            // [Wih_ctx | Whh]
__device__ float g_u[BB*1024];                         // [ctx(512) | h(512)]
__device__ float g_q[BB*HD];

// barrier state: per-block flag slots on separate 256B lines; no atomics.
__device__ volatile unsigned g_flag[128*64];
__device__ volatile unsigned g_dgen[64];
__device__ unsigned g_bar_epoch;

// ------------------------- math helpers --------------------------------------
__device__ __forceinline__ float ftanh(float x){
    float e = __expf(2.f*x);
    return 1.f - __fdividef(2.f, e + 1.f);
}
__device__ __forceinline__ float fsig(float x){
    return __fdividef(1.f, 1.f + __expf(-x));
}
__device__ __forceinline__ float tanha(float x){
    float y; asm("tanh.approx.f32 %0, %1;" : "=f"(y) : "f"(x)); return y;
}
__device__ __forceinline__ ull fdup(float x){
    ull r; asm("mov.b64 %0, {%1, %1};" : "=l"(r) : "f"(x)); return r;
}
__device__ __forceinline__ void fma2(ull& d, ull a, ull b){
    asm("fma.rn.f32x2 %0, %1, %2, %0;" : "+l"(d) : "l"(a), "l"(b));
}
__device__ __forceinline__ float2 upk(ull v){
    float2 f; asm("mov.b64 {%0, %1}, %2;" : "=f"(f.x), "=f"(f.y) : "l"(v));
    return f;
}

// flag barrier: arrival = 1 plain store to own line; block0 warp0 detects
// completion; release via generation word. Monotonic targets -> replay-safe.
__device__ __forceinline__ void dbar(unsigned tgt){
    __threadfence();
    __syncthreads();
    if (threadIdx.x == 0) g_flag[blockIdx.x << 6] = tgt;
    if (blockIdx.x == 0 && threadIdx.x < 32){
        for (;;){
            bool ok = true;
#pragma unroll
            for (int i = 0; i < 4; i++)
                ok &= ((unsigned)(g_flag[(threadIdx.x*4 + i) << 6] - tgt) < 0x80000000u);
            if (__all_sync(0xffffffffu, ok)) break;
        }
        if (threadIdx.x == 0){ __threadfence(); g_dgen[0] = tgt; }
    }
    if (threadIdx.x == 0){
        while ((unsigned)(g_dgen[0] - tgt) >= 0x80000000u) { }
        __threadfence();
    }
    __syncthreads();
}

#define CLUSTER_SYNC() do { \
    asm volatile("barrier.cluster.arrive.aligned;" ::: "memory"); \
    asm volatile("barrier.cluster.wait.aligned;"   ::: "memory"); \
} while(0)

// ------------------------- k_pre: fused gather-GEMMs + pack + init -----------
// z=0: enc fwd gates  (65536,1024) = gather(emb) @ Wih_f^T + b_f
// z=1: enc bwd gates
// z=2, by<254 : dec emb gates (16256,2048) = gather @ dec_Wih[:, :128]^T + dec_b
// z=2, by>=254: wcat pack, h_enc init, out[:,0,:]=0, barrier-epoch bump
__global__ void __launch_bounds__(256)
k_pre(const int* __restrict__ src, const int* __restrict__ trg,
      const float* __restrict__ enc_emb, const float* __restrict__ dec_emb,
      const float* __restrict__ Wih_f, const float* __restrict__ b_f,
      const float* __restrict__ Wih_b, const float* __restrict__ b_b,
      const float* __restrict__ dec_Wih, const float* __restrict__ dec_Whh,
      const float* __restrict__ dec_b, float* __restrict__ out)
{
    const int z = blockIdx.z, bx = blockIdx.x, by = blockIdx.y;
    const int tid = threadIdx.x;

    if (z == 2 && by >= 254){
        size_t idx = ((size_t)(by - 254)*32 + bx)*256 + tid;
        if (idx < (size_t)2048*1024){
            int n = idx >> 10, k = idx & 1023;
            g_wcat[idx] = (k < 512) ? dec_Wih[(size_t)n*640 + 128 + k]
                                    : dec_Whh[(size_t)n*512 + k - 512];
        } else if (idx < 2097152 + 65536){
            (&g_h_enc[0][0][0])[idx - 2097152] = 0.f;
        } else if (idx < 2162688 + 16384){
            size_t i3 = idx - 2162688;
            out[(i3 >> 7)*16384 + (i3 & 127)] = 0.f;
        } else if (idx == 2179072){
            g_bar_epoch += 4096u;
        }
        return;
    }
    if (z != 2 && bx >= 16) return;

    // ---- gather GEMM: 64 rows x 64 cols, K = 128 ----
    __shared__ int   toks[64];
    __shared__ float As[16][65];
    __shared__ __align__(8) float Bs[16][66];

    const float* emb;
    const float* W; const float* bias; float* C;
    int ldb, ldc, n0 = bx*64, m0 = by*64;
    if (z == 0){ emb = enc_emb; W = Wih_f;  bias = b_f;   C = g_xw_f; ldb = 128; ldc = 1024; }
    else if (z == 1){ emb = enc_emb; W = Wih_b; bias = b_b; C = g_xw_b; ldb = 128; ldc = 1024; }
    else { emb = dec_emb; W = dec_Wih; bias = dec_b; C = g_xg; ldb = 640; ldc = 2048; }

    if (tid < 64){
        int m = m0 + tid;
        toks[tid] = (z == 2) ? trg[(m & 127)*128 + (m >> 7)]
                             : src[(m & 127)*512 + (m >> 7)];
    }
    __syncthreads();

    const int tx = tid & 15, ty = tid >> 4;
    ull acc[4][2];
#pragma unroll
    for (int i=0;i<4;i++){ acc[i][0]=fdup(0.f); acc[i][1]=fdup(0.f); }

    for (int k0 = 0; k0 < 128; k0 += 16){
#pragma unroll 4
        for (int i = tid; i < 1024; i += 256){
            int mm = i >> 4, kk = i & 15;
            As[kk][mm] = emb[(size_t)toks[mm]*128 + k0 + kk];
        }
#pragma unroll 4
        for (int i = tid; i < 1024; i += 256){
            int nn = i >> 4, kk = i & 15;
            Bs[kk][nn] = W[(size_t)(n0+nn)*ldb + k0 + kk];
        }
        __syncthreads();
#pragma unroll
        for (int kk = 0; kk < 16; kk++){
            ull a2[4], b2[2];
#pragma unroll
            for (int i=0;i<4;i++) a2[i] = fdup(As[kk][ty + 16*i]);
            b2[0] = *(const ull*)&Bs[kk][2*tx];
            b2[1] = *(const ull*)&Bs[kk][2*tx + 32];
#pragma unroll
            for (int i=0;i<4;i++){
                fma2(acc[i][0], a2[i], b2[0]);
                fma2(acc[i][1], a2[i], b2[1]);
            }
        }
        __syncthreads();
    }
#pragma unroll
    for (int i=0;i<4;i++){
        int m = m0 + ty + 16*i;
#pragma unroll
        for (int jp=0;jp<2;jp++){
            int n = n0 + 2*tx + 32*jp;
            float2 v = upk(acc[i][jp]);
            v.x += bias[n]; v.y += bias[n+1];
            *(float2*)&C[(size_t)m*ldc + n] = v;
        }
    }
}

// ------------------------- enc_proj GEMM (bf16 A, bf16 out) ------------------
__global__ void __launch_bounds__(256)
sgemm_proj(const float* __restrict__ Bw, const float* __restrict__ bias)
{
    __shared__ float As[16][65];
    __shared__ __align__(8) float Bs[16][66];
    const int n0 = blockIdx.x * 64;
    const int m0 = blockIdx.y * 64;
    const int tid = threadIdx.x;
    const int tx = tid & 15, ty = tid >> 4;
    const __nv_bfloat16* A = (const __nv_bfloat16*)g_encout_bf;
    ull acc[4][2];
#pragma unroll
    for (int i=0;i<4;i++){ acc[i][0]=fdup(0.f); acc[i][1]=fdup(0.f); }

    for (int k0 = 0; k0 < 512; k0 += 16){
#pragma unroll 4
        for (int i = tid; i < 1024; i += 256){
            int mm = i >> 4, kk = i & 15;
            As[kk][mm] = __bfloat162float(A[(size_t)(m0+mm)*512 + k0 + kk]);
        }
#pragma unroll 4
        for (int i = tid; i < 1024; i += 256){
            int kk = i >> 6, nn = i & 63;
            Bs[kk][nn] = Bw[(size_t)(k0+kk)*512 + n0 + nn];
        }
        __syncthreads();
#pragma unroll
        for (int kk = 0; kk < 16; kk++){
            ull a2[4], b2[2];
#pragma unroll
            for (int i=0;i<4;i++) a2[i] = fdup(As[kk][ty + 16*i]);
            b2[0] = *(const ull*)&Bs[kk][2*tx];
            b2[1] = *(const ull*)&Bs[kk][2*tx + 32];
#pragma unroll
            for (int i=0;i<4;i++){
                fma2(acc[i][0], a2[i], b2[0]);
                fma2(acc[i][1], a2[i], b2[1]);
            }
        }
        __syncthreads();
    }
    __nv_bfloat16* Cb = (__nv_bfloat16*)g_encproj;
#pragma unroll
    for (int i=0;i<4;i++){
        int m = m0 + ty + 16*i;
#pragma unroll
        for (int jp=0;jp<2;jp++){
            int n = n0 + 2*tx + 32*jp;
            float2 v = upk(acc[i][jp]);
            v.x += bias[n]; v.y += bias[n+1];
            *(__nv_bfloat162*)&Cb[(size_t)m*512 + n] = __float22bfloat162_rn(v);
        }
    }
}

// ------------------------- persistent encoder --------------------------------
__global__ void __launch_bounds__(256) __cluster_dims__(8, 1, 1)
k_encoder(const float* __restrict__ Whh_f, const float* __restrict__ Whh_b)
{
    extern __shared__ float ws[];            // 256*132 floats
    __shared__ float hsf[256*18];
    const int bx  = blockIdx.x;
    const int jt  = bx & 7, bt = (bx >> 3) & 7, dir = bx >> 6;
    const int j0  = jt*32, b0 = bt*16;
    const int tid = threadIdx.x;
    const int tx  = tid & 31;
    const int ty  = tid >> 5;
    const float* __restrict__ Whh = dir ? Whh_b : Whh_f;
    const float* __restrict__ xw  = dir ? g_xw_b : g_xw_f;

#pragma unroll 4
    for (int i = tid; i < 32768; i += 256){
        int k = i & 255, nl = i >> 8;
        int jj = nl >> 2, g = nl & 3;
        ws[k*132 + nl] = Whh[(size_t)(g*256 + j0 + jj)*256 + k];
    }
    __syncthreads();

    float cr[2] = {0.f, 0.f};
    const int j = j0 + tx;

    for (int s = 0; s < 512; s++){
        const int sa = dir ? (511 - s) : s;
        const float* __restrict__ hin = g_h_enc[s & 1][dir];
        float* __restrict__ hout      = g_h_enc[(s & 1) ^ 1][dir];

#pragma unroll
        for (int i = tid; i < 4096; i += 256){
            int b = i >> 8, k = i & 255;
            hsf[k*18 + b] = __ldcg(&hin[(b0 + b)*256 + k]);
        }
        __syncthreads();

        ull accA[2], accB[2];
        accA[0]=fdup(0.f); accA[1]=fdup(0.f);
        accB[0]=fdup(0.f); accB[1]=fdup(0.f);

#pragma unroll 16
        for (int k = 0; k < 256; k++){
            const ull* wp = (const ull*)(ws + k*132 + 4*tx);
            ull w01 = wp[0], w23 = wp[1];
            float2 hp = *(const float2*)(hsf + k*18 + 2*ty);
            ull hd0 = fdup(hp.x), hd1 = fdup(hp.y);
            fma2(accA[0], w01, hd0);
            fma2(accB[0], w23, hd0);
            fma2(accA[1], w01, hd1);
            fma2(accB[1], w23, hd1);
        }
        __syncthreads();

#pragma unroll
        for (int r = 0; r < 2; r++){
            int b = b0 + 2*ty + r;
            float2 g01 = upk(accA[r]);
            float2 g23 = upk(accB[r]);
            const float* xwb = xw + ((size_t)sa*128 + b)*1024 + j;
            float ig = fsig (g01.x + xwb[0]);
            float fg = fsig (g01.y + xwb[256]);
            float gg = ftanh(g23.x + xwb[512]);
            float og = fsig (g23.y + xwb[768]);
            float cn = fmaf(fg, cr[r], ig*gg);
            cr[r] = cn;
            float hn = og * ftanh(cn);
            hout[b*256 + j] = hn;
            ((__nv_bfloat16*)g_encout_bf)[((size_t)b*512 + sa)*512 + dir*256 + j]
                = __float2bfloat16(hn);
        }
        if (s < 511){
            CLUSTER_SYNC();
        } else {
#pragma unroll
            for (int r = 0; r < 2; r++)
                g_c_enc[dir][(b0 + 2*ty + r)*256 + j] = cr[r];
        }
    }
}

// ------------------------- decoder tile GEMM (512 thr, prefetch) -------------
__device__ void tg512(const float* __restrict__ A, int lda,
                      const float* __restrict__ B, int ldb, int K,
                      int m0, int n0,
                      const float* __restrict__ bias,
                      float* __restrict__ C, int ldc)
{
    __shared__ float As[16][33];
    __shared__ __align__(8) float Bs[16][66];
    const int tid = threadIdx.x;
    const int tx = tid & 31, ty = tid >> 5;
    ull acc0 = fdup(0.f), acc1 = fdup(0.f);

    const int a_mm = tid >> 4, a_kk = tid & 15;
    const int b_kk0 = tid >> 6,        b_nn0 = tid & 63;
    const int b_kk1 = (tid+512) >> 6,  b_nn1 = tid & 63;
    float ra, rb0, rb1;
    ra  = __ldcg(&A[(size_t)(m0+a_mm)*lda + a_kk]);
    rb0 = B[(size_t)b_kk0*ldb + n0 + b_nn0];
    rb1 = B[(size_t)b_kk1*ldb + n0 + b_nn1];

    for (int k0 = 0; k0 < K; k0 += 16){
        As[a_kk][a_mm] = ra;
        Bs[b_kk0][b_nn0] = rb0;
        Bs[b_kk1][b_nn1] = rb1;
        __syncthreads();
        if (k0 + 16 < K){
            int kn = k0 + 16;
            ra  = __ldcg(&A[(size_t)(m0+a_mm)*lda + kn + a_kk]);
            rb0 = B[(size_t)(kn+b_kk0)*ldb + n0 + b_nn0];
            rb1 = B[(size_t)(kn+b_kk1)*ldb + n0 + b_nn1];
        }
#pragma unroll
        for (int kk = 0; kk < 16; kk++){
            ull bv = *(const ull*)&Bs[kk][2*tx];
            fma2(acc0, fdup(As[kk][ty]),      bv);
            fma2(acc1, fdup(As[kk][ty + 16]), bv);
        }
        __syncthreads();
    }
    {
        int n = n0 + 2*tx;
        float2 v0 = upk(acc0), v1 = upk(acc1);
        if (bias){
            float2 bb = *(const float2*)&bias[n];
            v0.x += bb.x; v0.y += bb.y; v1.x += bb.x; v1.y += bb.y;
        }
        *(float2*)&C[(size_t)(m0+ty)*ldc + n]    = v0;
        *(float2*)&C[(size_t)(m0+ty+16)*ldc + n] = v1;
    }
}

// ------------------------- fused gates + LSTM cell ---------------------------
// block (bq = bid>>5, jt = bid&31): 32 b-rows x 16 j x 4 gates, K = 1024.
// thread (tx = tid&15 -> j, ty = tid>>4 -> b). cell applied in-register.
__device__ void gates_cell(int bq, int jt, int t, float& cr)
{
    __shared__ float As[16][33];
    __shared__ __align__(8) float Bs[16][68];
    const int tid = threadIdx.x;
    const int tx = tid & 15, ty = tid >> 4;
    const int m0 = bq*32, j0 = jt*16;

    const int a_mm = tid >> 4, a_kk = tid & 15;
    const int b_nl0 = tid >> 4,         b_kk0 = tid & 15;
    const int b_nl1 = (tid + 512) >> 4, b_kk1 = tid & 15;
    const int brow0 = (b_nl0 & 3)*512 + j0 + (b_nl0 >> 2);
    const int brow1 = (b_nl1 & 3)*512 + j0 + (b_nl1 >> 2);
    const int bsp0 = b_nl0 + (b_nl0 >> 5)*2;     // bank-conflict pad
    const int bsp1 = b_nl1 + (b_nl1 >> 5)*2;

    ull acc01 = fdup(0.f), acc23 = fdup(0.f);
    float ra  = __ldcg(&g_u[(m0 + a_mm)*1024 + a_kk]);
    float rb0 = g_wcat[(size_t)brow0*1024 + b_kk0];
    float rb1 = g_wcat[(size_t)brow1*1024 + b_kk1];

    for (int k0 = 0; k0 < 1024; k0 += 16){
        As[a_kk][a_mm] = ra;
        Bs[b_kk0][bsp0] = rb0;
        Bs[b_kk1][bsp1] = rb1;
        __syncthreads();
        if (k0 + 16 < 1024){
            int kn = k0 + 16;
            ra  = __ldcg(&g_u[(m0 + a_mm)*1024 + kn + a_kk]);
            rb0 = g_wcat[(size_t)brow0*1024 + kn + b_kk0];
            rb1 = g_wcat[(size_t)brow1*1024 + kn + b_kk1];
        }
#pragma unroll
        for (int kk = 0; kk < 16; kk++){
            ull a = fdup(As[kk][ty]);
            const ull* wp = (const ull*)&Bs[kk][4*tx + (tx >> 3)*2];
            fma2(acc01, a, wp[0]);
            fma2(acc23, a, wp[1]);
        }
        __syncthreads();
    }
    const int b = m0 + ty, j = j0 + tx;
    const float* xgb = g_xg + (size_t)t*BB*2048 + (size_t)b*2048;
    float2 g01 = upk(acc01), g23 = upk(acc23);
    float ig = fsig (g01.x + xgb[j]);
    float fg = fsig (g01.y + xgb[512  + j]);
    float gg = ftanh(g23.x + xgb[1024 + j]);
    float og = fsig (g23.y + xgb[1536 + j]);
    float cn = fmaf(fg, cr, ig*gg);
    cr = cn;
    g_u[b*1024 + 512 + j] = og * ftanh(cn);
}

// ------------------------- decoder attention (512 thr) -----------------------
__device__ void attention(int b, const float* __restrict__ attn_v)
{
    __shared__ float qsh[512];
    __shared__ float sc[512];
    __shared__ float red[16];
    __shared__ float4 part[4][128];
    const int tid = threadIdx.x, lane = tid & 31, warp = tid >> 5;

    qsh[tid] = __ldcg(&g_q[b*512 + tid]);
    __syncthreads();

    float4 av[4], qv[4];
#pragma unroll
    for (int i = 0; i < 4; i++){
        av[i] = *(const float4*)&attn_v[4*(lane + 32*i)];
        qv[i] = *(const float4*)&qsh[4*(lane + 32*i)];
    }

    const __nv_bfloat162* __restrict__ proj = g_encproj + (size_t)b*512*256;
    for (int s = warp; s < 512; s += 16){
        const uint2* pr = (const uint2*)(proj + (size_t)s*256);
        float acc = 0.f;
#pragma unroll
        for (int i = 0; i < 4; i++){
            uint2 u = pr[lane + 32*i];
            float2 p0 = __bfloat1622float2(*(__nv_bfloat162*)&u.x);
            float2 p1 = __bfloat1622float2(*(__nv_bfloat162*)&u.y);
            acc = fmaf(av[i].x, tanha(qv[i].x + p0.x), acc);
            acc = fmaf(av[i].y, tanha(qv[i].y + p0.y), acc);
            acc = fmaf(av[i].z, tanha(qv[i].z + p1.x), acc);
            acc = fmaf(av[i].w, tanha(qv[i].w + p1.y), acc);
        }
#pragma unroll
        for (int o = 16; o; o >>= 1) acc += __shfl_xor_sync(~0u, acc, o);
        if (lane == 0) sc[s] = acc;
    }
    __syncthreads();

    float v = sc[tid];
    float m = v;
#pragma unroll
    for (int o = 16; o; o >>= 1) m = fmaxf(m, __shfl_xor_sync(~0u, m, o));
    if (lane == 0) red[warp] = m;
    __syncthreads();
    m = red[0];
#pragma unroll
    for (int i = 1; i < 16; i++) m = fmaxf(m, red[i]);
    __syncthreads();
    float ex = __expf(v - m);
    float ssum = ex;
#pragma unroll
    for (int o = 16; o; o >>= 1) ssum += __shfl_xor_sync(~0u, ssum, o);
    if (lane == 0) red[warp] = ssum;
    __syncthreads();
    ssum = 0.f;
#pragma unroll
    for (int i = 0; i < 16; i++) ssum += red[i];
    sc[tid] = ex * __fdividef(1.f, ssum);
    __syncthreads();

    const int q4 = tid >> 7, cp = tid & 127;
    const uint2* __restrict__ eo = (const uint2*)(g_encout_bf + (size_t)b*512*256);
    float4 ca = {0.f, 0.f, 0.f, 0.f};
#pragma unroll 4
    for (int s = q4*128; s < q4*128 + 128; s++){
        float w = sc[s];
        uint2 u = eo[(size_t)s*128 + cp];
        float2 f0 = __bfloat1622float2(*(__nv_bfloat162*)&u.x);
        float2 f1 = __bfloat1622float2(*(__nv_bfloat162*)&u.y);
        ca.x = fmaf(w, f0.x, ca.x);
        ca.y = fmaf(w, f0.y, ca.y);
        ca.z = fmaf(w, f1.x, ca.z);
        ca.w = fmaf(w, f1.y, ca.w);
    }
    part[q4][cp] = ca;
    __syncthreads();
    if (tid < 128){
        float4 p0 = part[0][tid], p1 = part[1][tid];
        float4 p2 = part[2][tid], p3 = part[3][tid];
        float4 r;
        r.x = p0.x + p1.x + p2.x + p3.x;
        r.y = p0.y + p1.y + p2.y + p3.y;
        r.z = p0.z + p1.z + p2.z + p3.z;
        r.w = p0.w + p1.w + p2.w + p3.w;
        *(float4*)&g_u[b*1024 + 4*tid] = r;
    }
    __syncthreads();
}

// ------------------------- persistent decoder (3 barriers/step) --------------
__global__ void __launch_bounds__(512)
k_decoder(const float* __restrict__ attn_W, const float* __restrict__ attn_v,
          const float* __restrict__ out_W, const float* __restrict__ out_b,
          float* __restrict__ out)
{
    const int bid = blockIdx.x, tid = threadIdx.x;
    const int bq = bid >> 5, jt = bid & 31;
    unsigned tgt = g_bar_epoch;

    float cr;
    {
        const int b = bq*32 + (tid >> 4), j = jt*16 + (tid & 15);
        float h;
        if (j < 256){ h = g_h_enc[0][0][b*256 + j];       cr = g_c_enc[0][b*256 + j]; }
        else        { h = g_h_enc[0][1][b*256 + j - 256]; cr = g_c_enc[1][b*256 + j - 256]; }
        g_u[b*1024 + 512 + j] = h;
    }
    tgt++; dbar(tgt);

    for (int t = 0; t < TT; t++){
        // ---- phase A: q = h@Wh (32 blocks); logits(prev h) (8 blocks, t>0) ----
        if (bid < 32){
            int mt = bid & 3, nt = bid >> 2;
            tg512(g_u + 512, 1024, attn_W, 512, 512,
                  mt*32, nt*64, nullptr, g_q, 512);
        } else if (bid < 40 && t > 0){
            int q = bid - 32, mt = q & 3, nt = q >> 2;
            tg512(g_u + 512, 1024, out_W, 128, 512,
                  mt*32, nt*64, out_b, out + (size_t)t*128, 16384);
        }
        tgt++; dbar(tgt);
        // ---- phase B: attention ----
        attention(bid, attn_v);
        tgt++; dbar(tgt);
        // ---- phase C+D: gates + cell fused ----
        gates_cell(bq, jt, t, cr);
        tgt++; dbar(tgt);
    }
    if (bid < 8){
        int mt = bid & 3, nt = bid >> 2;
        tg512(g_u + 512, 1024, out_W, 128, 512,
              mt*32, nt*64, out_b, out + (size_t)TT*128, 16384);
    }
}

// ------------------------- launch --------------------------------------------
extern "C" void kernel_launch(void* const* d_in, const int* in_sizes, int n_in,
                              void* d_out, int out_size)
{
    const int*   src     = (const int*)  d_in[0];
    const int*   trg     = (const int*)  d_in[1];
    const float* enc_emb = (const float*)d_in[2];
    const float* Wih_f   = (const float*)d_in[3];
    const float* Whh_f   = (const float*)d_in[4];
    const float* b_f     = (const float*)d_in[5];
    const float* Wih_b   = (const float*)d_in[6];
    const float* Whh_b   = (const float*)d_in[7];
    const float* b_b     = (const float*)d_in[8];
    const float* dec_emb = (const float*)d_in[9];
    const float* dec_Wih = (const float*)d_in[10];
    const float* dec_Whh = (const float*)d_in[11];
    const float* dec_b   = (const float*)d_in[12];
    const float* attn_W  = (const float*)d_in[13];
    const float* attn_b  = (const float*)d_in[14];
    const float* attn_v  = (const float*)d_in[15];
    const float* out_W   = (const float*)d_in[16];
    const float* out_b   = (const float*)d_in[17];
    float* out = (float*)d_out;

    cudaFuncSetAttribute(k_encoder,
        cudaFuncAttributeMaxDynamicSharedMemorySize, 256*132*4);

    // 1) fused prep + input-gate GEMMs (gathers embeddings inline)
    k_pre<<<dim3(32, 1024, 3), 256>>>(src, trg, enc_emb, dec_emb,
                                      Wih_f, b_f, Wih_b, b_b,
                                      dec_Wih, dec_Whh, dec_b, out);
    // 2) persistent encoder
    k_encoder<<<128, 256, 256*132*4>>>(Whh_f, Whh_b);
    // 3) enc_proj = enc_out(bf16) @ We + attn_b -> bf16
    sgemm_proj<<<dim3(512/64, (BB*SS)/64), 256>>>(attn_W + 512*512, attn_b);
    // 4) persistent decoder
    k_decoder<<<128, 512>>>(attn_W, attn_v, out_W, out_b, out);
}

// round 10
// speedup vs baseline: 1.0032x; 1.0032x over previous
#include <cuda_runtime.h>
#include <cuda_bf16.h>
#include <cstdint>
#include <cstddef>

#define BB  128
#define SS  512
#define EE  128
#define HH  256
#define HD  512
#define TT  127

typedef unsigned long long ull;

// ------------------------- device scratch ------------------------------------
__device__ float g_xw_f[(size_t)SS*BB*4*HH];
__device__ float g_xw_b[(size_t)SS*BB*4*HH];
__device__ float g_h_enc[2][2][BB*HH];                 // [parity][dir]
__device__ float g_c_enc[2][BB*HH];                    // final cells [dir]
__device__ __nv_bfloat162 g_encout_bf[(size_t)BB*SS*256]; // (b,s,512) bf16
__device__ __nv_bfloat162 g_encproj[(size_t)BB*SS*256];   // bf16 + attn_b
__device__ float g_xg[(size_t)TT*BB*4*HD];
__device__ float g_wcat[(size_t)4*HD*1024];            // [Wih_ctx | Whh]
__device__ float g_u[BB*1024];                         // [ctx(512) | h(512)]
__device__ float g_q[BB*HD];

// barrier state: per-block flag slots on separate 256B lines; no atomics.
__device__ volatile unsigned g_flag[128*64];
__device__ volatile unsigned g_dgen[64];
__device__ unsigned g_bar_epoch;

// ------------------------- math helpers --------------------------------------
__device__ __forceinline__ float ftanh(float x){
    float e = __expf(2.f*x);
    return 1.f - __fdividef(2.f, e + 1.f);
}
__device__ __forceinline__ float fsig(float x){
    return __fdividef(1.f, 1.f + __expf(-x));
}
__device__ __forceinline__ float tanha(float x){
    float y; asm("tanh.approx.f32 %0, %1;" : "=f"(y) : "f"(x)); return y;
}
__device__ __forceinline__ ull fdup(float x){
    ull r; asm("mov.b64 %0, {%1, %1};" : "=l"(r) : "f"(x)); return r;
}
__device__ __forceinline__ void fma2(ull& d, ull a, ull b){
    asm("fma.rn.f32x2 %0, %1, %2, %0;" : "+l"(d) : "l"(a), "l"(b));
}
__device__ __forceinline__ float2 upk(ull v){
    float2 f; asm("mov.b64 {%0, %1}, %2;" : "=f"(f.x), "=f"(f.y) : "l"(v));
    return f;
}

// flag barrier (replay-safe monotonic targets)
__device__ __forceinline__ void dbar(unsigned tgt){
    __threadfence();
    __syncthreads();
    if (threadIdx.x == 0) g_flag[blockIdx.x << 6] = tgt;
    if (blockIdx.x == 0 && threadIdx.x < 32){
        for (;;){
            bool ok = true;
#pragma unroll
            for (int i = 0; i < 4; i++)
                ok &= ((unsigned)(g_flag[(threadIdx.x*4 + i) << 6] - tgt) < 0x80000000u);
            if (__all_sync(0xffffffffu, ok)) break;
        }
        if (threadIdx.x == 0){ __threadfence(); g_dgen[0] = tgt; }
    }
    if (threadIdx.x == 0){
        while ((unsigned)(g_dgen[0] - tgt) >= 0x80000000u) __nanosleep(32);
        __threadfence();
    }
    __syncthreads();
}

#define CLUSTER_SYNC() do { \
    asm volatile("barrier.cluster.arrive.aligned;" ::: "memory"); \
    asm volatile("barrier.cluster.wait.aligned;"   ::: "memory"); \
} while(0)

// ------------------------- k_pre: fused gather-GEMMs + pack + init -----------
__global__ void __launch_bounds__(256)
k_pre(const int* __restrict__ src, const int* __restrict__ trg,
      const float* __restrict__ enc_emb, const float* __restrict__ dec_emb,
      const float* __restrict__ Wih_f, const float* __restrict__ b_f,
      const float* __restrict__ Wih_b, const float* __restrict__ b_b,
      const float* __restrict__ dec_Wih, const float* __restrict__ dec_Whh,
      const float* __restrict__ dec_b, float* __restrict__ out)
{
    const int z = blockIdx.z, bx = blockIdx.x, by = blockIdx.y;
    const int tid = threadIdx.x;

    if (z == 2 && by >= 254){
        size_t idx = ((size_t)(by - 254)*32 + bx)*256 + tid;
        if (idx < (size_t)2048*1024){
            int n = idx >> 10, k = idx & 1023;
            g_wcat[idx] = (k < 512) ? dec_Wih[(size_t)n*640 + 128 + k]
                                    : dec_Whh[(size_t)n*512 + k - 512];
        } else if (idx < 2097152 + 65536){
            (&g_h_enc[0][0][0])[idx - 2097152] = 0.f;
        } else if (idx < 2162688 + 16384){
            size_t i3 = idx - 2162688;
            out[(i3 >> 7)*16384 + (i3 & 127)] = 0.f;
        } else if (idx == 2179072){
            g_bar_epoch += 4096u;
        }
        return;
    }
    if (z != 2 && bx >= 16) return;

    __shared__ int   toks[64];
    __shared__ float As[16][65];
    __shared__ __align__(8) float Bs[16][66];

    const float* emb;
    const float* W; const float* bias; float* C;
    int ldb, ldc, n0 = bx*64, m0 = by*64;
    if (z == 0){ emb = enc_emb; W = Wih_f;  bias = b_f;   C = g_xw_f; ldb = 128; ldc = 1024; }
    else if (z == 1){ emb = enc_emb; W = Wih_b; bias = b_b; C = g_xw_b; ldb = 128; ldc = 1024; }
    else { emb = dec_emb; W = dec_Wih; bias = dec_b; C = g_xg; ldb = 640; ldc = 2048; }

    if (tid < 64){
        int m = m0 + tid;
        toks[tid] = (z == 2) ? trg[(m & 127)*128 + (m >> 7)]
                             : src[(m & 127)*512 + (m >> 7)];
    }
    __syncthreads();

    const int tx = tid & 15, ty = tid >> 4;
    ull acc[4][2];
#pragma unroll
    for (int i=0;i<4;i++){ acc[i][0]=fdup(0.f); acc[i][1]=fdup(0.f); }

    for (int k0 = 0; k0 < 128; k0 += 16){
#pragma unroll 4
        for (int i = tid; i < 1024; i += 256){
            int mm = i >> 4, kk = i & 15;
            As[kk][mm] = emb[(size_t)toks[mm]*128 + k0 + kk];
        }
#pragma unroll 4
        for (int i = tid; i < 1024; i += 256){
            int nn = i >> 4, kk = i & 15;
            Bs[kk][nn] = W[(size_t)(n0+nn)*ldb + k0 + kk];
        }
        __syncthreads();
#pragma unroll
        for (int kk = 0; kk < 16; kk++){
            ull a2[4], b2[2];
#pragma unroll
            for (int i=0;i<4;i++) a2[i] = fdup(As[kk][ty + 16*i]);
            b2[0] = *(const ull*)&Bs[kk][2*tx];
            b2[1] = *(const ull*)&Bs[kk][2*tx + 32];
#pragma unroll
            for (int i=0;i<4;i++){
                fma2(acc[i][0], a2[i], b2[0]);
                fma2(acc[i][1], a2[i], b2[1]);
            }
        }
        __syncthreads();
    }
#pragma unroll
    for (int i=0;i<4;i++){
        int m = m0 + ty + 16*i;
#pragma unroll
        for (int jp=0;jp<2;jp++){
            int n = n0 + 2*tx + 32*jp;
            float2 v = upk(acc[i][jp]);
            v.x += bias[n]; v.y += bias[n+1];
            *(float2*)&C[(size_t)m*ldc + n] = v;
        }
    }
}

// ------------------------- enc_proj GEMM (bf16 A, bf16 out) ------------------
__global__ void __launch_bounds__(256)
sgemm_proj(const float* __restrict__ Bw, const float* __restrict__ bias)
{
    __shared__ float As[16][65];
    __shared__ __align__(8) float Bs[16][66];
    const int n0 = blockIdx.x * 64;
    const int m0 = blockIdx.y * 64;
    const int tid = threadIdx.x;
    const int tx = tid & 15, ty = tid >> 4;
    const __nv_bfloat16* A = (const __nv_bfloat16*)g_encout_bf;
    ull acc[4][2];
#pragma unroll
    for (int i=0;i<4;i++){ acc[i][0]=fdup(0.f); acc[i][1]=fdup(0.f); }

    for (int k0 = 0; k0 < 512; k0 += 16){
#pragma unroll 4
        for (int i = tid; i < 1024; i += 256){
            int mm = i >> 4, kk = i & 15;
            As[kk][mm] = __bfloat162float(A[(size_t)(m0+mm)*512 + k0 + kk]);
        }
#pragma unroll 4
        for (int i = tid; i < 1024; i += 256){
            int kk = i >> 6, nn = i & 63;
            Bs[kk][nn] = Bw[(size_t)(k0+kk)*512 + n0 + nn];
        }
        __syncthreads();
#pragma unroll
        for (int kk = 0; kk < 16; kk++){
            ull a2[4], b2[2];
#pragma unroll
            for (int i=0;i<4;i++) a2[i] = fdup(As[kk][ty + 16*i]);
            b2[0] = *(const ull*)&Bs[kk][2*tx];
            b2[1] = *(const ull*)&Bs[kk][2*tx + 32];
#pragma unroll
            for (int i=0;i<4;i++){
                fma2(acc[i][0], a2[i], b2[0]);
                fma2(acc[i][1], a2[i], b2[1]);
            }
        }
        __syncthreads();
    }
    __nv_bfloat16* Cb = (__nv_bfloat16*)g_encproj;
#pragma unroll
    for (int i=0;i<4;i++){
        int m = m0 + ty + 16*i;
#pragma unroll
        for (int jp=0;jp<2;jp++){
            int n = n0 + 2*tx + 32*jp;
            float2 v = upk(acc[i][jp]);
            v.x += bias[n]; v.y += bias[n+1];
            *(__nv_bfloat162*)&Cb[(size_t)m*512 + n] = __float22bfloat162_rn(v);
        }
    }
}

// ------------------------- persistent encoder --------------------------------
__global__ void __launch_bounds__(256) __cluster_dims__(8, 1, 1)
k_encoder(const float* __restrict__ Whh_f, const float* __restrict__ Whh_b)
{
    extern __shared__ float ws[];            // 256*132 floats
    __shared__ float hsf[256*18];
    const int bx  = blockIdx.x;
    const int jt  = bx & 7, bt = (bx >> 3) & 7, dir = bx >> 6;
    const int j0  = jt*32, b0 = bt*16;
    const int tid = threadIdx.x;
    const int tx  = tid & 31;
    const int ty  = tid >> 5;
    const float* __restrict__ Whh = dir ? Whh_b : Whh_f;
    const float* __restrict__ xw  = dir ? g_xw_b : g_xw_f;

#pragma unroll 4
    for (int i = tid; i < 32768; i += 256){
        int k = i & 255, nl = i >> 8;
        int jj = nl >> 2, g = nl & 3;
        ws[k*132 + nl] = Whh[(size_t)(g*256 + j0 + jj)*256 + k];
    }
    __syncthreads();

    float cr[2] = {0.f, 0.f};
    const int j = j0 + tx;

    for (int s = 0; s < 512; s++){
        const int sa = dir ? (511 - s) : s;
        const float* __restrict__ hin = g_h_enc[s & 1][dir];
        float* __restrict__ hout      = g_h_enc[(s & 1) ^ 1][dir];

#pragma unroll
        for (int i = tid; i < 4096; i += 256){
            int b = i >> 8, k = i & 255;
            hsf[k*18 + b] = __ldcg(&hin[(b0 + b)*256 + k]);
        }
        __syncthreads();

        ull accA[2], accB[2];
        accA[0]=fdup(0.f); accA[1]=fdup(0.f);
        accB[0]=fdup(0.f); accB[1]=fdup(0.f);

#pragma unroll 16
        for (int k = 0; k < 256; k++){
            const ull* wp = (const ull*)(ws + k*132 + 4*tx);
            ull w01 = wp[0], w23 = wp[1];
            float2 hp = *(const float2*)(hsf + k*18 + 2*ty);
            ull hd0 = fdup(hp.x), hd1 = fdup(hp.y);
            fma2(accA[0], w01, hd0);
            fma2(accB[0], w23, hd0);
            fma2(accA[1], w01, hd1);
            fma2(accB[1], w23, hd1);
        }
        __syncthreads();

#pragma unroll
        for (int r = 0; r < 2; r++){
            int b = b0 + 2*ty + r;
            float2 g01 = upk(accA[r]);
            float2 g23 = upk(accB[r]);
            const float* xwb = xw + ((size_t)sa*128 + b)*1024 + j;
            float ig = fsig (g01.x + xwb[0]);
            float fg = fsig (g01.y + xwb[256]);
            float gg = ftanh(g23.x + xwb[512]);
            float og = fsig (g23.y + xwb[768]);
            float cn = fmaf(fg, cr[r], ig*gg);
            cr[r] = cn;
            float hn = og * ftanh(cn);
            hout[b*256 + j] = hn;
            ((__nv_bfloat16*)g_encout_bf)[((size_t)b*512 + sa)*512 + dir*256 + j]
                = __float2bfloat16(hn);
        }
        if (s < 511){
            CLUSTER_SYNC();
        } else {
#pragma unroll
            for (int r = 0; r < 2; r++)
                g_c_enc[dir][(b0 + 2*ty + r)*256 + j] = cr[r];
        }
    }
}

// ------------------------- decoder tile GEMM (512 thr, depth-2 prefetch) -----
__device__ void tg512(const float* __restrict__ A, int lda,
                      const float* __restrict__ B, int ldb, int K,
                      int m0, int n0,
                      const float* __restrict__ bias,
                      float* __restrict__ C, int ldc)
{
    __shared__ float As[16][33];
    __shared__ __align__(8) float Bs[16][66];
    const int tid = threadIdx.x;
    const int tx = tid & 31, ty = tid >> 5;
    ull acc0 = fdup(0.f), acc1 = fdup(0.f);

    const int a_mm = tid >> 4, a_kk = tid & 15;
    const int b_kk0 = tid >> 6,        b_nn0 = tid & 63;
    const int b_kk1 = (tid+512) >> 6,  b_nn1 = tid & 63;
    const int ntile = K >> 4;
    float ra[2], rb0[2], rb1[2];
#pragma unroll
    for (int p = 0; p < 2; p++){
        int k0 = p*16;
        ra[p]  = __ldcg(&A[(size_t)(m0+a_mm)*lda + k0 + a_kk]);
        rb0[p] = B[(size_t)(k0+b_kk0)*ldb + n0 + b_nn0];
        rb1[p] = B[(size_t)(k0+b_kk1)*ldb + n0 + b_nn1];
    }

    for (int it = 0; it < ntile; it++){
        const int cur = it & 1;
        As[a_kk][a_mm]   = ra[cur];
        Bs[b_kk0][b_nn0] = rb0[cur];
        Bs[b_kk1][b_nn1] = rb1[cur];
        __syncthreads();
        if (it + 2 < ntile){
            int kn = (it + 2) << 4;
            ra[cur]  = __ldcg(&A[(size_t)(m0+a_mm)*lda + kn + a_kk]);
            rb0[cur] = B[(size_t)(kn+b_kk0)*ldb + n0 + b_nn0];
            rb1[cur] = B[(size_t)(kn+b_kk1)*ldb + n0 + b_nn1];
        }
#pragma unroll
        for (int kk = 0; kk < 16; kk++){
            ull bv = *(const ull*)&Bs[kk][2*tx];
            fma2(acc0, fdup(As[kk][ty]),      bv);
            fma2(acc1, fdup(As[kk][ty + 16]), bv);
        }
        __syncthreads();
    }
    {
        int n = n0 + 2*tx;
        float2 v0 = upk(acc0), v1 = upk(acc1);
        if (bias){
            float2 bb = *(const float2*)&bias[n];
            v0.x += bb.x; v0.y += bb.y; v1.x += bb.x; v1.y += bb.y;
        }
        *(float2*)&C[(size_t)(m0+ty)*ldc + n]    = v0;
        *(float2*)&C[(size_t)(m0+ty+16)*ldc + n] = v1;
    }
}

// ------------------------- fused gates + LSTM cell (depth-2 prefetch) --------
__device__ void gates_cell(int bq, int jt, int t, float& cr)
{
    __shared__ float As[16][33];
    __shared__ __align__(8) float Bs[16][68];
    const int tid = threadIdx.x;
    const int tx = tid & 15, ty = tid >> 4;
    const int m0 = bq*32, j0 = jt*16;

    const int a_mm = tid >> 4, a_kk = tid & 15;
    const int b_nl0 = tid >> 4,         b_kk0 = tid & 15;
    const int b_nl1 = (tid + 512) >> 4, b_kk1 = tid & 15;
    const int brow0 = (b_nl0 & 3)*512 + j0 + (b_nl0 >> 2);
    const int brow1 = (b_nl1 & 3)*512 + j0 + (b_nl1 >> 2);
    const int bsp0 = b_nl0 + (b_nl0 >> 5)*2;
    const int bsp1 = b_nl1 + (b_nl1 >> 5)*2;

    ull acc01 = fdup(0.f), acc23 = fdup(0.f);
    float ra[2], rb0[2], rb1[2];
#pragma unroll
    for (int p = 0; p < 2; p++){
        int k0 = p*16;
        ra[p]  = __ldcg(&g_u[(m0 + a_mm)*1024 + k0 + a_kk]);
        rb0[p] = g_wcat[(size_t)brow0*1024 + k0 + b_kk0];
        rb1[p] = g_wcat[(size_t)brow1*1024 + k0 + b_kk1];
    }

    for (int it = 0; it < 64; it++){
        const int cur = it & 1;
        As[a_kk][a_mm] = ra[cur];
        Bs[b_kk0][bsp0] = rb0[cur];
        Bs[b_kk1][bsp1] = rb1[cur];
        __syncthreads();
        if (it + 2 < 64){
            int kn = (it + 2) << 4;
            ra[cur]  = __ldcg(&g_u[(m0 + a_mm)*1024 + kn + a_kk]);
            rb0[cur] = g_wcat[(size_t)brow0*1024 + kn + b_kk0];
            rb1[cur] = g_wcat[(size_t)brow1*1024 + kn + b_kk1];
        }
#pragma unroll
        for (int kk = 0; kk < 16; kk++){
            ull a = fdup(As[kk][ty]);
            const ull* wp = (const ull*)&Bs[kk][4*tx + (tx >> 3)*2];
            fma2(acc01, a, wp[0]);
            fma2(acc23, a, wp[1]);
        }
        __syncthreads();
    }
    const int b = m0 + ty, j = j0 + tx;
    const float* xgb = g_xg + (size_t)t*BB*2048 + (size_t)b*2048;
    float2 g01 = upk(acc01), g23 = upk(acc23);
    float ig = fsig (g01.x + xgb[j]);
    float fg = fsig (g01.y + xgb[512  + j]);
    float gg = ftanh(g23.x + xgb[1024 + j]);
    float og = fsig (g23.y + xgb[1536 + j]);
    float cn = fmaf(fg, cr, ig*gg);
    cr = cn;
    g_u[b*1024 + 512 + j] = og * ftanh(cn);
}

// ------------------------- decoder attention (deep-MLP streaming) ------------
__device__ __forceinline__ float dot8(uint4 u, const float* qv, const float* av,
                                      float acc){
    float2 p;
    p = __bfloat1622float2(*(__nv_bfloat162*)&u.x);
    acc = fmaf(av[0], tanha(qv[0] + p.x), acc);
    acc = fmaf(av[1], tanha(qv[1] + p.y), acc);
    p = __bfloat1622float2(*(__nv_bfloat162*)&u.y);
    acc = fmaf(av[2], tanha(qv[2] + p.x), acc);
    acc = fmaf(av[3], tanha(qv[3] + p.y), acc);
    p = __bfloat1622float2(*(__nv_bfloat162*)&u.z);
    acc = fmaf(av[4], tanha(qv[4] + p.x), acc);
    acc = fmaf(av[5], tanha(qv[5] + p.y), acc);
    p = __bfloat1622float2(*(__nv_bfloat162*)&u.w);
    acc = fmaf(av[6], tanha(qv[6] + p.x), acc);
    acc = fmaf(av[7], tanha(qv[7] + p.y), acc);
    return acc;
}

__device__ void attention(int b, const float* __restrict__ attn_v)
{
    __shared__ float qsh[512];
    __shared__ float sc[512];
    __shared__ float red[16];
    __shared__ float part[8][520];
    const int tid = threadIdx.x, lane = tid & 31, warp = tid >> 5;

    qsh[tid] = __ldcg(&g_q[b*512 + tid]);
    __syncthreads();

    // per-lane constants: elems [16*lane, 16*lane+16)
    float qv[16], av[16];
#pragma unroll
    for (int i = 0; i < 16; i++){
        qv[i] = qsh[16*lane + i];
        av[i] = attn_v[16*lane + i];
    }

    // ---- scores: warp does rows (warp+16i, warp+16i+256), prefetch next pair
    const uint4* __restrict__ pr = (const uint4*)(g_encproj + (size_t)b*512*256);
    uint4 c0a, c0b, c1a, c1b;
    {
        int s0 = warp, s1 = warp + 256;
        c0a = pr[s0*64 + 2*lane]; c0b = pr[s0*64 + 2*lane + 1];
        c1a = pr[s1*64 + 2*lane]; c1b = pr[s1*64 + 2*lane + 1];
    }
    for (int i = 0; i < 16; i++){
        uint4 n0a, n0b, n1a, n1b;
        if (i < 15){
            int s0 = warp + 16*(i+1), s1 = s0 + 256;
            n0a = pr[s0*64 + 2*lane]; n0b = pr[s0*64 + 2*lane + 1];
            n1a = pr[s1*64 + 2*lane]; n1b = pr[s1*64 + 2*lane + 1];
        }
        float a0 = 0.f, a1 = 0.f;
        a0 = dot8(c0a, qv,     av,     a0);
        a0 = dot8(c0b, qv + 8, av + 8, a0);
        a1 = dot8(c1a, qv,     av,     a1);
        a1 = dot8(c1b, qv + 8, av + 8, a1);
#pragma unroll
        for (int o = 16; o; o >>= 1){
            a0 += __shfl_xor_sync(~0u, a0, o);
            a1 += __shfl_xor_sync(~0u, a1, o);
        }
        if (lane == 0){ sc[warp + 16*i] = a0; sc[warp + 16*i + 256] = a1; }
        c0a = n0a; c0b = n0b; c1a = n1a; c1b = n1b;
    }
    __syncthreads();

    // ---- softmax ----
    float v = sc[tid];
    float m = v;
#pragma unroll
    for (int o = 16; o; o >>= 1) m = fmaxf(m, __shfl_xor_sync(~0u, m, o));
    if (lane == 0) red[warp] = m;
    __syncthreads();
    m = red[0];
#pragma unroll
    for (int i = 1; i < 16; i++) m = fmaxf(m, red[i]);
    __syncthreads();
    float ex = __expf(v - m);
    float ssum = ex;
#pragma unroll
    for (int o = 16; o; o >>= 1) ssum += __shfl_xor_sync(~0u, ssum, o);
    if (lane == 0) red[warp] = ssum;
    __syncthreads();
    ssum = 0.f;
#pragma unroll
    for (int i = 0; i < 16; i++) ssum += red[i];
    sc[tid] = ex * __fdividef(1.f, ssum);
    __syncthreads();

    // ---- context: thread = (s-group tid>>6) x (e-chunk tid&63), unroll 8 ----
    const uint4* __restrict__ eo = (const uint4*)(g_encout_bf + (size_t)b*512*256);
    const int sg = tid >> 6, ec = tid & 63;
    float a0=0.f,a1=0.f,a2=0.f,a3=0.f,a4=0.f,a5=0.f,a6=0.f,a7=0.f;
#pragma unroll 8
    for (int i = 0; i < 64; i++){
        int s = sg*64 + i;
        float w = sc[s];
        uint4 u = eo[s*64 + ec];
        float2 p;
        p = __bfloat1622float2(*(__nv_bfloat162*)&u.x);
        a0 = fmaf(w, p.x, a0); a1 = fmaf(w, p.y, a1);
        p = __bfloat1622float2(*(__nv_bfloat162*)&u.y);
        a2 = fmaf(w, p.x, a2); a3 = fmaf(w, p.y, a3);
        p = __bfloat1622float2(*(__nv_bfloat162*)&u.z);
        a4 = fmaf(w, p.x, a4); a5 = fmaf(w, p.y, a5);
        p = __bfloat1622float2(*(__nv_bfloat162*)&u.w);
        a6 = fmaf(w, p.x, a6); a7 = fmaf(w, p.y, a7);
    }
    float4 w0 = {a0,a1,a2,a3}, w1 = {a4,a5,a6,a7};
    *(float4*)&part[sg][ec*8]     = w0;
    *(float4*)&part[sg][ec*8 + 4] = w1;
    __syncthreads();
    if (tid < 128){
        float4 r = {0.f,0.f,0.f,0.f};
#pragma unroll
        for (int g = 0; g < 8; g++){
            float4 p = *(const float4*)&part[g][tid*4];
            r.x += p.x; r.y += p.y; r.z += p.z; r.w += p.w;
        }
        *(float4*)&g_u[b*1024 + 4*tid] = r;
    }
    __syncthreads();
}

// ------------------------- persistent decoder --------------------------------
__global__ void __launch_bounds__(512)
k_decoder(const float* __restrict__ attn_W, const float* __restrict__ attn_v,
          const float* __restrict__ out_W, const float* __restrict__ out_b,
          float* __restrict__ out)
{
    const int bid = blockIdx.x, tid = threadIdx.x;
    const int bq = bid >> 5, jt = bid & 31;
    unsigned tgt = g_bar_epoch;

    float cr;
    {
        const int b = bq*32 + (tid >> 4), j = jt*16 + (tid & 15);
        float h;
        if (j < 256){ h = g_h_enc[0][0][b*256 + j];       cr = g_c_enc[0][b*256 + j]; }
        else        { h = g_h_enc[0][1][b*256 + j - 256]; cr = g_c_enc[1][b*256 + j - 256]; }
        g_u[b*1024 + 512 + j] = h;
    }
    tgt++; dbar(tgt);

    for (int t = 0; t < TT; t++){
        if (bid < 32){
            int mt = bid & 3, nt = bid >> 2;
            tg512(g_u + 512, 1024, attn_W, 512, 512,
                  mt*32, nt*64, nullptr, g_q, 512);
        } else if (bid < 40 && t > 0){
            int q = bid - 32, mt = q & 3, nt = q >> 2;
            tg512(g_u + 512, 1024, out_W, 128, 512,
                  mt*32, nt*64, out_b, out + (size_t)t*128, 16384);
        }
        tgt++; dbar(tgt);
        attention(bid, attn_v);
        tgt++; dbar(tgt);
        gates_cell(bq, jt, t, cr);
        tgt++; dbar(tgt);
    }
    if (bid < 8){
        int mt = bid & 3, nt = bid >> 2;
        tg512(g_u + 512, 1024, out_W, 128, 512,
              mt*32, nt*64, out_b, out + (size_t)TT*128, 16384);
    }
}

// ------------------------- launch --------------------------------------------
extern "C" void kernel_launch(void* const* d_in, const int* in_sizes, int n_in,
                              void* d_out, int out_size)
{
    const int*   src     = (const int*)  d_in[0];
    const int*   trg     = (const int*)  d_in[1];
    const float* enc_emb = (const float*)d_in[2];
    const float* Wih_f   = (const float*)d_in[3];
    const float* Whh_f   = (const float*)d_in[4];
    const float* b_f     = (const float*)d_in[5];
    const float* Wih_b   = (const float*)d_in[6];
    const float* Whh_b   = (const float*)d_in[7];
    const float* b_b     = (const float*)d_in[8];
    const float* dec_emb = (const float*)d_in[9];
    const float* dec_Wih = (const float*)d_in[10];
    const float* dec_Whh = (const float*)d_in[11];
    const float* dec_b   = (const float*)d_in[12];
    const float* attn_W  = (const float*)d_in[13];
    const float* attn_b  = (const float*)d_in[14];
    const float* attn_v  = (const float*)d_in[15];
    const float* out_W   = (const float*)d_in[16];
    const float* out_b   = (const float*)d_in[17];
    float* out = (float*)d_out;

    cudaFuncSetAttribute(k_encoder,
        cudaFuncAttributeMaxDynamicSharedMemorySize, 256*132*4);

    // 1) fused prep + input-gate GEMMs
    k_pre<<<dim3(32, 1024, 3), 256>>>(src, trg, enc_emb, dec_emb,
                                      Wih_f, b_f, Wih_b, b_b,
                                      dec_Wih, dec_Whh, dec_b, out);
    // 2) persistent encoder
    k_encoder<<<128, 256, 256*132*4>>>(Whh_f, Whh_b);
    // 3) enc_proj = enc_out(bf16) @ We + attn_b -> bf16
    sgemm_proj<<<dim3(512/64, (BB*SS)/64), 256>>>(attn_W + 512*512, attn_b);
    // 4) persistent decoder
    k_decoder<<<128, 512>>>(attn_W, attn_v, out_W, out_b, out);
}

// round 14
// speedup vs baseline: 1.0775x; 1.0740x over previous
#include <cuda_runtime.h>
#include <cuda_bf16.h>
#include <cstdint>
#include <cstddef>

#define BB  128
#define SS  512
#define EE  128
#define HH  256
#define HD  512
#define TT  127

typedef unsigned long long ull;

// ------------------------- device scratch ------------------------------------
__device__ float g_xw_f[(size_t)SS*BB*4*HH];
__device__ float g_xw_b[(size_t)SS*BB*4*HH];
__device__ float g_h_enc[2][2][BB*HH];                 // [parity][dir]
__device__ float g_c_enc[2][BB*HH];                    // final cells [dir]
__device__ __nv_bfloat162 g_encout_bf[(size_t)BB*SS*256]; // (b,s,512) bf16
__device__ __nv_bfloat162 g_encproj[(size_t)BB*SS*256];   // bf16 + attn_b
__device__ float g_xg[(size_t)TT*BB*4*HD];
__device__ float g_wcat[(size_t)4*HD*1024];            // [Wih_ctx | Whh]
__device__ float g_u[BB*1024];                         // [ctx(512) | h(512)]
__device__ float g_q[BB*HD];

// barrier state: per-block flag slots on separate 256B lines; no atomics.
__device__ volatile unsigned g_flag[128*64];
__device__ volatile unsigned g_dgen[64];
__device__ unsigned g_bar_epoch;

// ------------------------- math helpers --------------------------------------
__device__ __forceinline__ float ftanh(float x){
    float e = __expf(2.f*x);
    return 1.f - __fdividef(2.f, e + 1.f);
}
__device__ __forceinline__ float fsig(float x){
    return __fdividef(1.f, 1.f + __expf(-x));
}
__device__ __forceinline__ ull fdup(float x){
    ull r; asm("mov.b64 %0, {%1, %1};" : "=l"(r) : "f"(x)); return r;
}
__device__ __forceinline__ void fma2(ull& d, ull a, ull b){
    asm("fma.rn.f32x2 %0, %1, %2, %0;" : "+l"(d) : "l"(a), "l"(b));
}
__device__ __forceinline__ float2 upk(ull v){
    float2 f; asm("mov.b64 {%0, %1}, %2;" : "=f"(f.x), "=f"(f.y) : "l"(v));
    return f;
}
// bf16x2 ops for the score pass
__device__ __forceinline__ uint32_t hadd2b(uint32_t a, uint32_t b){
    uint32_t r; asm("add.rn.bf16x2 %0, %1, %2;" : "=r"(r) : "r"(a), "r"(b));
    return r;
}
__device__ __forceinline__ uint32_t tanh2b(uint32_t a){
    uint32_t r; asm("tanh.approx.bf16x2 %0, %1;" : "=r"(r) : "r"(a));
    return r;
}
__device__ __forceinline__ uint32_t packbf2(float lo, float hi){
    uint32_t r; asm("cvt.rn.bf16x2.f32 %0, %1, %2;" : "=r"(r) : "f"(hi), "f"(lo));
    return r;
}
// L2 cache-steered 256-bit loads (sm_103a requires v4.b64 for evict policy)
__device__ __forceinline__ ulonglong4 ldg_el64(const void* p){
    ulonglong4 u;
    asm volatile("ld.global.nc.L2::evict_last.v4.u64 {%0,%1,%2,%3}, [%4];"
                 : "=l"(u.x), "=l"(u.y), "=l"(u.z), "=l"(u.w) : "l"(p));
    return u;
}
__device__ __forceinline__ ulonglong4 ldg_ef64(const void* p){
    ulonglong4 u;
    asm volatile("ld.global.nc.L2::evict_first.v4.u64 {%0,%1,%2,%3}, [%4];"
                 : "=l"(u.x), "=l"(u.y), "=l"(u.z), "=l"(u.w) : "l"(p));
    return u;
}

// flag barrier (replay-safe monotonic targets)
__device__ __forceinline__ void dbar(unsigned tgt){
    __threadfence();
    __syncthreads();
    if (threadIdx.x == 0) g_flag[blockIdx.x << 6] = tgt;
    if (blockIdx.x == 0 && threadIdx.x < 32){
        for (;;){
            bool ok = true;
#pragma unroll
            for (int i = 0; i < 4; i++)
                ok &= ((unsigned)(g_flag[(threadIdx.x*4 + i) << 6] - tgt) < 0x80000000u);
            if (__all_sync(0xffffffffu, ok)) break;
        }
        if (threadIdx.x == 0){ __threadfence(); g_dgen[0] = tgt; }
    }
    if (threadIdx.x == 0){
        while ((unsigned)(g_dgen[0] - tgt) >= 0x80000000u) __nanosleep(32);
        __threadfence();
    }
    __syncthreads();
}

#define CLUSTER_SYNC() do { \
    asm volatile("barrier.cluster.arrive.aligned;" ::: "memory"); \
    asm volatile("barrier.cluster.wait.aligned;"   ::: "memory"); \
} while(0)

// ------------------------- k_pre: fused gather-GEMMs + pack + init -----------
__global__ void __launch_bounds__(256)
k_pre(const int* __restrict__ src, const int* __restrict__ trg,
      const float* __restrict__ enc_emb, const float* __restrict__ dec_emb,
      const float* __restrict__ Wih_f, const float* __restrict__ b_f,
      const float* __restrict__ Wih_b, const float* __restrict__ b_b,
      const float* __restrict__ dec_Wih, const float* __restrict__ dec_Whh,
      const float* __restrict__ dec_b, float* __restrict__ out)
{
    const int z = blockIdx.z, bx = blockIdx.x, by = blockIdx.y;
    const int tid = threadIdx.x;

    if (z == 2 && by >= 254){
        size_t idx = ((size_t)(by - 254)*32 + bx)*256 + tid;
        if (idx < (size_t)2048*1024){
            int n = idx >> 10, k = idx & 1023;
            g_wcat[idx] = (k < 512) ? dec_Wih[(size_t)n*640 + 128 + k]
                                    : dec_Whh[(size_t)n*512 + k - 512];
        } else if (idx < 2097152 + 65536){
            (&g_h_enc[0][0][0])[idx - 2097152] = 0.f;
        } else if (idx < 2162688 + 16384){
            size_t i3 = idx - 2162688;
            out[(i3 >> 7)*16384 + (i3 & 127)] = 0.f;
        } else if (idx == 2179072){
            g_bar_epoch += 4096u;
        }
        return;
    }
    if (z != 2 && bx >= 16) return;

    __shared__ int   toks[64];
    __shared__ float As[16][65];
    __shared__ __align__(8) float Bs[16][66];

    const float* emb;
    const float* W; const float* bias; float* C;
    int ldb, ldc, n0 = bx*64, m0 = by*64;
    if (z == 0){ emb = enc_emb; W = Wih_f;  bias = b_f;   C = g_xw_f; ldb = 128; ldc = 1024; }
    else if (z == 1){ emb = enc_emb; W = Wih_b; bias = b_b; C = g_xw_b; ldb = 128; ldc = 1024; }
    else { emb = dec_emb; W = dec_Wih; bias = dec_b; C = g_xg; ldb = 640; ldc = 2048; }

    if (tid < 64){
        int m = m0 + tid;
        toks[tid] = (z == 2) ? trg[(m & 127)*128 + (m >> 7)]
                             : src[(m & 127)*512 + (m >> 7)];
    }
    __syncthreads();

    const int tx = tid & 15, ty = tid >> 4;
    ull acc[4][2];
#pragma unroll
    for (int i=0;i<4;i++){ acc[i][0]=fdup(0.f); acc[i][1]=fdup(0.f); }

    for (int k0 = 0; k0 < 128; k0 += 16){
#pragma unroll 4
        for (int i = tid; i < 1024; i += 256){
            int mm = i >> 4, kk = i & 15;
            As[kk][mm] = emb[(size_t)toks[mm]*128 + k0 + kk];
        }
#pragma unroll 4
        for (int i = tid; i < 1024; i += 256){
            int nn = i >> 4, kk = i & 15;
            Bs[kk][nn] = W[(size_t)(n0+nn)*ldb + k0 + kk];
        }
        __syncthreads();
#pragma unroll
        for (int kk = 0; kk < 16; kk++){
            ull a2[4], b2[2];
#pragma unroll
            for (int i=0;i<4;i++) a2[i] = fdup(As[kk][ty + 16*i]);
            b2[0] = *(const ull*)&Bs[kk][2*tx];
            b2[1] = *(const ull*)&Bs[kk][2*tx + 32];
#pragma unroll
            for (int i=0;i<4;i++){
                fma2(acc[i][0], a2[i], b2[0]);
                fma2(acc[i][1], a2[i], b2[1]);
            }
        }
        __syncthreads();
    }
#pragma unroll
    for (int i=0;i<4;i++){
        int m = m0 + ty + 16*i;
#pragma unroll
        for (int jp=0;jp<2;jp++){
            int n = n0 + 2*tx + 32*jp;
            float2 v = upk(acc[i][jp]);
            v.x += bias[n]; v.y += bias[n+1];
            *(float2*)&C[(size_t)m*ldc + n] = v;
        }
    }
}

// ------------------------- enc_proj GEMM (bf16 A, bf16 out) ------------------
__global__ void __launch_bounds__(256)
sgemm_proj(const float* __restrict__ Bw, const float* __restrict__ bias)
{
    __shared__ float As[16][65];
    __shared__ __align__(8) float Bs[16][66];
    const int n0 = blockIdx.x * 64;
    const int m0 = blockIdx.y * 64;
    const int tid = threadIdx.x;
    const int tx = tid & 15, ty = tid >> 4;
    const __nv_bfloat16* A = (const __nv_bfloat16*)g_encout_bf;
    ull acc[4][2];
#pragma unroll
    for (int i=0;i<4;i++){ acc[i][0]=fdup(0.f); acc[i][1]=fdup(0.f); }

    for (int k0 = 0; k0 < 512; k0 += 16){
#pragma unroll 4
        for (int i = tid; i < 1024; i += 256){
            int mm = i >> 4, kk = i & 15;
            As[kk][mm] = __bfloat162float(A[(size_t)(m0+mm)*512 + k0 + kk]);
        }
#pragma unroll 4
        for (int i = tid; i < 1024; i += 256){
            int kk = i >> 6, nn = i & 63;
            Bs[kk][nn] = Bw[(size_t)(k0+kk)*512 + n0 + nn];
        }
        __syncthreads();
#pragma unroll
        for (int kk = 0; kk < 16; kk++){
            ull a2[4], b2[2];
#pragma unroll
            for (int i=0;i<4;i++) a2[i] = fdup(As[kk][ty + 16*i]);
            b2[0] = *(const ull*)&Bs[kk][2*tx];
            b2[1] = *(const ull*)&Bs[kk][2*tx + 32];
#pragma unroll
            for (int i=0;i<4;i++){
                fma2(acc[i][0], a2[i], b2[0]);
                fma2(acc[i][1], a2[i], b2[1]);
            }
        }
        __syncthreads();
    }
    __nv_bfloat16* Cb = (__nv_bfloat16*)g_encproj;
#pragma unroll
    for (int i=0;i<4;i++){
        int m = m0 + ty + 16*i;
#pragma unroll
        for (int jp=0;jp<2;jp++){
            int n = n0 + 2*tx + 32*jp;
            float2 v = upk(acc[i][jp]);
            v.x += bias[n]; v.y += bias[n+1];
            *(__nv_bfloat162*)&Cb[(size_t)m*512 + n] = __float22bfloat162_rn(v);
        }
    }
}

// ------------------------- persistent encoder --------------------------------
__global__ void __launch_bounds__(256) __cluster_dims__(8, 1, 1)
k_encoder(const float* __restrict__ Whh_f, const float* __restrict__ Whh_b)
{
    extern __shared__ float ws[];            // 256*132 floats
    __shared__ float hsf[256*18];
    const int bx  = blockIdx.x;
    const int jt  = bx & 7, bt = (bx >> 3) & 7, dir = bx >> 6;
    const int j0  = jt*32, b0 = bt*16;
    const int tid = threadIdx.x;
    const int tx  = tid & 31;
    const int ty  = tid >> 5;
    const float* __restrict__ Whh = dir ? Whh_b : Whh_f;
    const float* __restrict__ xw  = dir ? g_xw_b : g_xw_f;

#pragma unroll 4
    for (int i = tid; i < 32768; i += 256){
        int k = i & 255, nl = i >> 8;
        int jj = nl >> 2, g = nl & 3;
        ws[k*132 + nl] = Whh[(size_t)(g*256 + j0 + jj)*256 + k];
    }
    __syncthreads();

    float cr[2] = {0.f, 0.f};
    const int j = j0 + tx;

    for (int s = 0; s < 512; s++){
        const int sa = dir ? (511 - s) : s;
        const float* __restrict__ hin = g_h_enc[s & 1][dir];
        float* __restrict__ hout      = g_h_enc[(s & 1) ^ 1][dir];

#pragma unroll
        for (int i = tid; i < 4096; i += 256){
            int b = i >> 8, k = i & 255;
            hsf[k*18 + b] = __ldcg(&hin[(b0 + b)*256 + k]);
        }
        __syncthreads();

        ull accA[2], accB[2];
        accA[0]=fdup(0.f); accA[1]=fdup(0.f);
        accB[0]=fdup(0.f); accB[1]=fdup(0.f);

#pragma unroll 16
        for (int k = 0; k < 256; k++){
            const ull* wp = (const ull*)(ws + k*132 + 4*tx);
            ull w01 = wp[0], w23 = wp[1];
            float2 hp = *(const float2*)(hsf + k*18 + 2*ty);
            ull hd0 = fdup(hp.x), hd1 = fdup(hp.y);
            fma2(accA[0], w01, hd0);
            fma2(accB[0], w23, hd0);
            fma2(accA[1], w01, hd1);
            fma2(accB[1], w23, hd1);
        }
        __syncthreads();

#pragma unroll
        for (int r = 0; r < 2; r++){
            int b = b0 + 2*ty + r;
            float2 g01 = upk(accA[r]);
            float2 g23 = upk(accB[r]);
            const float* xwb = xw + ((size_t)sa*128 + b)*1024 + j;
            float ig = fsig (g01.x + xwb[0]);
            float fg = fsig (g01.y + xwb[256]);
            float gg = ftanh(g23.x + xwb[512]);
            float og = fsig (g23.y + xwb[768]);
            float cn = fmaf(fg, cr[r], ig*gg);
            cr[r] = cn;
            float hn = og * ftanh(cn);
            hout[b*256 + j] = hn;
            ((__nv_bfloat16*)g_encout_bf)[((size_t)b*512 + sa)*512 + dir*256 + j]
                = __float2bfloat16(hn);
        }
        if (s < 511){
            CLUSTER_SYNC();
        } else {
#pragma unroll
            for (int r = 0; r < 2; r++)
                g_c_enc[dir][(b0 + 2*ty + r)*256 + j] = cr[r];
        }
    }
}

// ------------------------- decoder tile GEMM (512 thr, depth-2 prefetch) -----
__device__ void tg512(const float* __restrict__ A, int lda,
                      const float* __restrict__ B, int ldb, int K,
                      int m0, int n0,
                      const float* __restrict__ bias,
                      float* __restrict__ C, int ldc)
{
    __shared__ float As[16][33];
    __shared__ __align__(8) float Bs[16][66];
    const int tid = threadIdx.x;
    const int tx = tid & 31, ty = tid >> 5;
    ull acc0 = fdup(0.f), acc1 = fdup(0.f);

    const int a_mm = tid >> 4, a_kk = tid & 15;
    const int b_kk0 = tid >> 6,        b_nn0 = tid & 63;
    const int b_kk1 = (tid+512) >> 6,  b_nn1 = tid & 63;
    const int ntile = K >> 4;
    float ra[2], rb0[2], rb1[2];
#pragma unroll
    for (int p = 0; p < 2; p++){
        int k0 = p*16;
        ra[p]  = __ldcg(&A[(size_t)(m0+a_mm)*lda + k0 + a_kk]);
        rb0[p] = B[(size_t)(k0+b_kk0)*ldb + n0 + b_nn0];
        rb1[p] = B[(size_t)(k0+b_kk1)*ldb + n0 + b_nn1];
    }

    for (int it = 0; it < ntile; it++){
        const int cur = it & 1;
        As[a_kk][a_mm]   = ra[cur];
        Bs[b_kk0][b_nn0] = rb0[cur];
        Bs[b_kk1][b_nn1] = rb1[cur];
        __syncthreads();
        if (it + 2 < ntile){
            int kn = (it + 2) << 4;
            ra[cur]  = __ldcg(&A[(size_t)(m0+a_mm)*lda + kn + a_kk]);
            rb0[cur] = B[(size_t)(kn+b_kk0)*ldb + n0 + b_nn0];
            rb1[cur] = B[(size_t)(kn+b_kk1)*ldb + n0 + b_nn1];
        }
#pragma unroll
        for (int kk = 0; kk < 16; kk++){
            ull bv = *(const ull*)&Bs[kk][2*tx];
            fma2(acc0, fdup(As[kk][ty]),      bv);
            fma2(acc1, fdup(As[kk][ty + 16]), bv);
        }
        __syncthreads();
    }
    {
        int n = n0 + 2*tx;
        float2 v0 = upk(acc0), v1 = upk(acc1);
        if (bias){
            float2 bb = *(const float2*)&bias[n];
            v0.x += bb.x; v0.y += bb.y; v1.x += bb.x; v1.y += bb.y;
        }
        *(float2*)&C[(size_t)(m0+ty)*ldc + n]    = v0;
        *(float2*)&C[(size_t)(m0+ty+16)*ldc + n] = v1;
    }
}

// ------------------------- fused gates + LSTM cell (depth-2 prefetch) --------
__device__ void gates_cell(int bq, int jt, int t, float& cr)
{
    __shared__ float As[16][33];
    __shared__ __align__(8) float Bs[16][68];
    const int tid = threadIdx.x;
    const int tx = tid & 15, ty = tid >> 4;
    const int m0 = bq*32, j0 = jt*16;

    const int a_mm = tid >> 4, a_kk = tid & 15;
    const int b_nl0 = tid >> 4,         b_kk0 = tid & 15;
    const int b_nl1 = (tid + 512) >> 4, b_kk1 = tid & 15;
    const int brow0 = (b_nl0 & 3)*512 + j0 + (b_nl0 >> 2);
    const int brow1 = (b_nl1 & 3)*512 + j0 + (b_nl1 >> 2);
    const int bsp0 = b_nl0 + (b_nl0 >> 5)*2;
    const int bsp1 = b_nl1 + (b_nl1 >> 5)*2;

    ull acc01 = fdup(0.f), acc23 = fdup(0.f);
    float ra[2], rb0[2], rb1[2];
#pragma unroll
    for (int p = 0; p < 2; p++){
        int k0 = p*16;
        ra[p]  = __ldcg(&g_u[(m0 + a_mm)*1024 + k0 + a_kk]);
        rb0[p] = g_wcat[(size_t)brow0*1024 + k0 + b_kk0];
        rb1[p] = g_wcat[(size_t)brow1*1024 + k0 + b_kk1];
    }

    for (int it = 0; it < 64; it++){
        const int cur = it & 1;
        As[a_kk][a_mm] = ra[cur];
        Bs[b_kk0][bsp0] = rb0[cur];
        Bs[b_kk1][bsp1] = rb1[cur];
        __syncthreads();
        if (it + 2 < 64){
            int kn = (it + 2) << 4;
            ra[cur]  = __ldcg(&g_u[(m0 + a_mm)*1024 + kn + a_kk]);
            rb0[cur] = g_wcat[(size_t)brow0*1024 + kn + b_kk0];
            rb1[cur] = g_wcat[(size_t)brow1*1024 + kn + b_kk1];
        }
#pragma unroll
        for (int kk = 0; kk < 16; kk++){
            ull a = fdup(As[kk][ty]);
            const ull* wp = (const ull*)&Bs[kk][4*tx + (tx >> 3)*2];
            fma2(acc01, a, wp[0]);
            fma2(acc23, a, wp[1]);
        }
        __syncthreads();
    }
    const int b = m0 + ty, j = j0 + tx;
    const float* xgb = g_xg + (size_t)t*BB*2048 + (size_t)b*2048;
    float2 g01 = upk(acc01), g23 = upk(acc23);
    float ig = fsig (g01.x + xgb[j]);
    float fg = fsig (g01.y + xgb[512  + j]);
    float gg = ftanh(g23.x + xgb[1024 + j]);
    float og = fsig (g23.y + xgb[1536 + j]);
    float cn = fmaf(fg, cr, ig*gg);
    cr = cn;
    g_u[b*1024 + 512 + j] = og * ftanh(cn);
}

// ------------------------- decoder attention (bf16x2 tanh + L2 steering) -----
__device__ __forceinline__ float dot16b(ulonglong4 u, const uint32_t* q2,
                                        const float* av, float acc){
    const uint32_t* w = (const uint32_t*)&u;
#pragma unroll
    for (int p = 0; p < 8; p++){
        uint32_t s = tanh2b(hadd2b(w[p], q2[p]));
        float lo = __uint_as_float(s << 16);
        float hi = __uint_as_float(s & 0xFFFF0000u);
        acc = fmaf(av[2*p],     lo, acc);
        acc = fmaf(av[2*p + 1], hi, acc);
    }
    return acc;
}

__device__ void attention(int b, const float* __restrict__ attn_v)
{
    __shared__ float qsh[512];
    __shared__ float sc[512];
    __shared__ float red[16];
    __shared__ float partc[16*512];      // 32 KB context partials
    const int tid = threadIdx.x, lane = tid & 31, warp = tid >> 5;

    qsh[tid] = __ldcg(&g_q[b*512 + tid]);
    __syncthreads();

    // per-lane constants: elems [16*lane, 16*lane+16) as bf16x2 + f32
    uint32_t qv2[8];
    float av[16];
#pragma unroll
    for (int i = 0; i < 8; i++){
        float lo = qsh[16*lane + 2*i], hi = qsh[16*lane + 2*i + 1];
        qv2[i] = packbf2(lo, hi);
    }
#pragma unroll
    for (int i = 0; i < 16; i++) av[i] = attn_v[16*lane + i];

    // ---- scores: warp handles rows (warp+16i, warp+16i+256); proj pinned in L2
    const char* __restrict__ prb = (const char*)(g_encproj + (size_t)b*512*256);
    ulonglong4 c0, c1;
    {
        int s0 = warp, s1 = warp + 256;
        c0 = ldg_el64(prb + s0*1024 + lane*32);
        c1 = ldg_el64(prb + s1*1024 + lane*32);
    }
    for (int i = 0; i < 16; i++){
        ulonglong4 n0, n1;
        if (i < 15){
            int s0 = warp + 16*(i+1), s1 = s0 + 256;
            n0 = ldg_el64(prb + s0*1024 + lane*32);
            n1 = ldg_el64(prb + s1*1024 + lane*32);
        }
        float a0 = dot16b(c0, qv2, av, 0.f);
        float a1 = dot16b(c1, qv2, av, 0.f);
#pragma unroll
        for (int o = 16; o; o >>= 1){
            a0 += __shfl_xor_sync(~0u, a0, o);
            a1 += __shfl_xor_sync(~0u, a1, o);
        }
        if (lane == 0){ sc[warp + 16*i] = a0; sc[warp + 16*i + 256] = a1; }
        c0 = n0; c1 = n1;
    }
    __syncthreads();

    // ---- softmax ----
    float v = sc[tid];
    float m = v;
#pragma unroll
    for (int o = 16; o; o >>= 1) m = fmaxf(m, __shfl_xor_sync(~0u, m, o));
    if (lane == 0) red[warp] = m;
    __syncthreads();
    m = red[0];
#pragma unroll
    for (int i = 1; i < 16; i++) m = fmaxf(m, red[i]);
    __syncthreads();
    float ex = __expf(v - m);
    float ssum = ex;
#pragma unroll
    for (int o = 16; o; o >>= 1) ssum += __shfl_xor_sync(~0u, ssum, o);
    if (lane == 0) red[warp] = ssum;
    __syncthreads();
    ssum = 0.f;
#pragma unroll
    for (int i = 0; i < 16; i++) ssum += red[i];
    sc[tid] = ex * __fdividef(1.f, ssum);
    __syncthreads();

    // ---- context: 16 s-groups x 32 e-chunks of 32B; encout streams (evict_first)
    const char* __restrict__ eob = (const char*)(g_encout_bf + (size_t)b*512*256);
    const int sg = tid >> 5, ec = tid & 31;
    float a[16];
#pragma unroll
    for (int k = 0; k < 16; k++) a[k] = 0.f;
#pragma unroll 8
    for (int i = 0; i < 32; i++){
        int s = sg*32 + i;
        float w = sc[s];
        ulonglong4 u = ldg_ef64(eob + (size_t)s*1024 + ec*32);
        const uint32_t* ww = (const uint32_t*)&u;
#pragma unroll
        for (int p = 0; p < 8; p++){
            float2 f = __bfloat1622float2(*(__nv_bfloat162*)&ww[p]);
            a[2*p]     = fmaf(w, f.x, a[2*p]);
            a[2*p + 1] = fmaf(w, f.y, a[2*p + 1]);
        }
    }
#pragma unroll
    for (int k = 0; k < 16; k += 4)
        *(float4*)&partc[sg*512 + ec*16 + k] = *(float4*)&a[k];
    __syncthreads();
    {
        float r = 0.f;
#pragma unroll
        for (int g = 0; g < 16; g++) r += partc[g*512 + tid];
        g_u[b*1024 + tid] = r;
    }
    __syncthreads();
}

// ------------------------- persistent decoder --------------------------------
__global__ void __launch_bounds__(512)
k_decoder(const float* __restrict__ attn_W, const float* __restrict__ attn_v,
          const float* __restrict__ out_W, const float* __restrict__ out_b,
          float* __restrict__ out)
{
    const int bid = blockIdx.x, tid = threadIdx.x;
    const int bq = bid >> 5, jt = bid & 31;
    unsigned tgt = g_bar_epoch;

    float cr;
    {
        const int b = bq*32 + (tid >> 4), j = jt*16 + (tid & 15);
        float h;
        if (j < 256){ h = g_h_enc[0][0][b*256 + j];       cr = g_c_enc[0][b*256 + j]; }
        else        { h = g_h_enc[0][1][b*256 + j - 256]; cr = g_c_enc[1][b*256 + j - 256]; }
        g_u[b*1024 + 512 + j] = h;
    }
    tgt++; dbar(tgt);

    for (int t = 0; t < TT; t++){
        if (bid < 32){
            int mt = bid & 3, nt = bid >> 2;
            tg512(g_u + 512, 1024, attn_W, 512, 512,
                  mt*32, nt*64, nullptr, g_q, 512);
        } else if (bid < 40 && t > 0){
            int q = bid - 32, mt = q & 3, nt = q >> 2;
            tg512(g_u + 512, 1024, out_W, 128, 512,
                  mt*32, nt*64, out_b, out + (size_t)t*128, 16384);
        }
        tgt++; dbar(tgt);
        attention(bid, attn_v);
        tgt++; dbar(tgt);
        gates_cell(bq, jt, t, cr);
        tgt++; dbar(tgt);
    }
    if (bid < 8){
        int mt = bid & 3, nt = bid >> 2;
        tg512(g_u + 512, 1024, out_W, 128, 512,
              mt*32, nt*64, out_b, out + (size_t)TT*128, 16384);
    }
}

// ------------------------- launch --------------------------------------------
extern "C" void kernel_launch(void* const* d_in, const int* in_sizes, int n_in,
                              void* d_out, int out_size)
{
    const int*   src     = (const int*)  d_in[0];
    const int*   trg     = (const int*)  d_in[1];
    const float* enc_emb = (const float*)d_in[2];
    const float* Wih_f   = (const float*)d_in[3];
    const float* Whh_f   = (const float*)d_in[4];
    const float* b_f     = (const float*)d_in[5];
    const float* Wih_b   = (const float*)d_in[6];
    const float* Whh_b   = (const float*)d_in[7];
    const float* b_b     = (const float*)d_in[8];
    const float* dec_emb = (const float*)d_in[9];
    const float* dec_Wih = (const float*)d_in[10];
    const float* dec_Whh = (const float*)d_in[11];
    const float* dec_b   = (const float*)d_in[12];
    const float* attn_W  = (const float*)d_in[13];
    const float* attn_b  = (const float*)d_in[14];
    const float* attn_v  = (const float*)d_in[15];
    const float* out_W   = (const float*)d_in[16];
    const float* out_b   = (const float*)d_in[17];
    float* out = (float*)d_out;

    cudaFuncSetAttribute(k_encoder,
        cudaFuncAttributeMaxDynamicSharedMemorySize, 256*132*4);

    // 1) fused prep + input-gate GEMMs
    k_pre<<<dim3(32, 1024, 3), 256>>>(src, trg, enc_emb, dec_emb,
                                      Wih_f, b_f, Wih_b, b_b,
                                      dec_Wih, dec_Whh, dec_b, out);
    // 2) persistent encoder
    k_encoder<<<128, 256, 256*132*4>>>(Whh_f, Whh_b);
    // 3) enc_proj = enc_out(bf16) @ We + attn_b -> bf16
    sgemm_proj<<<dim3(512/64, (BB*SS)/64), 256>>>(attn_W + 512*512, attn_b);
    // 4) persistent decoder
    k_decoder<<<128, 512>>>(attn_W, attn_v, out_W, out_b, out);
}

// round 15
// speedup vs baseline: 1.2123x; 1.1251x over previous
#include <cuda_runtime.h>
#include <cuda_bf16.h>
#include <cstdint>
#include <cstddef>

#define BB  128
#define SS  512
#define EE  128
#define HH  256
#define HD  512
#define TT  127

typedef unsigned long long ull;

// ------------------------- device scratch ------------------------------------
__device__ float g_xw_f[(size_t)SS*BB*4*HH];
__device__ float g_xw_b[(size_t)SS*BB*4*HH];
__device__ float g_h_enc[2][2][BB*HH];                 // [parity][dir]
__device__ float g_c_enc[2][BB*HH];                    // final cells [dir]
__device__ __nv_bfloat162 g_encout_bf[(size_t)BB*SS*256]; // (b,s,512) bf16
__device__ __nv_bfloat162 g_encproj[(size_t)BB*SS*256];   // bf16 + attn_b
__device__ float g_xg[(size_t)TT*BB*4*HD];
__device__ float g_wcat[(size_t)4*HD*1024];            // [Wih_ctx | Whh]
__device__ float g_u[BB*1024];                         // [ctx(512) | h(512)]
__device__ float g_q[BB*HD];

// barrier state: per-block flag slots on separate 256B lines; no atomics.
__device__ volatile unsigned g_flag[128*64];
__device__ volatile unsigned g_dgen[64];
__device__ unsigned g_bar_epoch;

// ------------------------- math helpers --------------------------------------
__device__ __forceinline__ float ftanh(float x){
    float e = __expf(2.f*x);
    return 1.f - __fdividef(2.f, e + 1.f);
}
__device__ __forceinline__ float fsig(float x){
    return __fdividef(1.f, 1.f + __expf(-x));
}
__device__ __forceinline__ ull fdup(float x){
    ull r; asm("mov.b64 %0, {%1, %1};" : "=l"(r) : "f"(x)); return r;
}
__device__ __forceinline__ void fma2(ull& d, ull a, ull b){
    asm("fma.rn.f32x2 %0, %1, %2, %0;" : "+l"(d) : "l"(a), "l"(b));
}
__device__ __forceinline__ float2 upk(ull v){
    float2 f; asm("mov.b64 {%0, %1}, %2;" : "=f"(f.x), "=f"(f.y) : "l"(v));
    return f;
}
// bf16x2 ops for the score pass
__device__ __forceinline__ uint32_t hadd2b(uint32_t a, uint32_t b){
    uint32_t r; asm("add.rn.bf16x2 %0, %1, %2;" : "=r"(r) : "r"(a), "r"(b));
    return r;
}
__device__ __forceinline__ uint32_t tanh2b(uint32_t a){
    uint32_t r; asm("tanh.approx.bf16x2 %0, %1;" : "=r"(r) : "r"(a));
    return r;
}
__device__ __forceinline__ uint32_t packbf2(float lo, float hi){
    uint32_t r; asm("cvt.rn.bf16x2.f32 %0, %1, %2;" : "=r"(r) : "f"(hi), "f"(lo));
    return r;
}
// L2 cache-steered 256-bit loads (sm_103a requires v4.b64 for evict policy)
__device__ __forceinline__ ulonglong4 ldg_el64(const void* p){
    ulonglong4 u;
    asm volatile("ld.global.nc.L2::evict_last.v4.u64 {%0,%1,%2,%3}, [%4];"
                 : "=l"(u.x), "=l"(u.y), "=l"(u.z), "=l"(u.w) : "l"(p));
    return u;
}
__device__ __forceinline__ ulonglong4 ldg_ef64(const void* p){
    ulonglong4 u;
    asm volatile("ld.global.nc.L2::evict_first.v4.u64 {%0,%1,%2,%3}, [%4];"
                 : "=l"(u.x), "=l"(u.y), "=l"(u.z), "=l"(u.w) : "l"(p));
    return u;
}

// flag barrier (replay-safe monotonic targets)
__device__ __forceinline__ void dbar(unsigned tgt){
    __threadfence();
    __syncthreads();
    if (threadIdx.x == 0) g_flag[blockIdx.x << 6] = tgt;
    if (blockIdx.x == 0 && threadIdx.x < 32){
        for (;;){
            bool ok = true;
#pragma unroll
            for (int i = 0; i < 4; i++)
                ok &= ((unsigned)(g_flag[(threadIdx.x*4 + i) << 6] - tgt) < 0x80000000u);
            if (__all_sync(0xffffffffu, ok)) break;
        }
        if (threadIdx.x == 0){ __threadfence(); g_dgen[0] = tgt; }
    }
    if (threadIdx.x == 0){
        while ((unsigned)(g_dgen[0] - tgt) >= 0x80000000u) __nanosleep(32);
        __threadfence();
    }
    __syncthreads();
}

#define CLUSTER_SYNC() do { \
    asm volatile("barrier.cluster.arrive.aligned;" ::: "memory"); \
    asm volatile("barrier.cluster.wait.aligned;"   ::: "memory"); \
} while(0)

// ------------------------- k_pre: fused gather-GEMMs + pack + init -----------
__global__ void __launch_bounds__(256)
k_pre(const int* __restrict__ src, const int* __restrict__ trg,
      const float* __restrict__ enc_emb, const float* __restrict__ dec_emb,
      const float* __restrict__ Wih_f, const float* __restrict__ b_f,
      const float* __restrict__ Wih_b, const float* __restrict__ b_b,
      const float* __restrict__ dec_Wih, const float* __restrict__ dec_Whh,
      const float* __restrict__ dec_b, float* __restrict__ out)
{
    const int z = blockIdx.z, bx = blockIdx.x, by = blockIdx.y;
    const int tid = threadIdx.x;

    if (z == 2 && by >= 254){
        size_t idx = ((size_t)(by - 254)*32 + bx)*256 + tid;
        if (idx < (size_t)2048*1024){
            int n = idx >> 10, k = idx & 1023;
            g_wcat[idx] = (k < 512) ? dec_Wih[(size_t)n*640 + 128 + k]
                                    : dec_Whh[(size_t)n*512 + k - 512];
        } else if (idx < 2097152 + 65536){
            (&g_h_enc[0][0][0])[idx - 2097152] = 0.f;
        } else if (idx < 2162688 + 16384){
            size_t i3 = idx - 2162688;
            out[(i3 >> 7)*16384 + (i3 & 127)] = 0.f;
        } else if (idx == 2179072){
            g_bar_epoch += 4096u;
        }
        return;
    }
    if (z != 2 && bx >= 16) return;

    __shared__ int   toks[64];
    __shared__ float As[16][65];
    __shared__ __align__(8) float Bs[16][66];

    const float* emb;
    const float* W; const float* bias; float* C;
    int ldb, ldc, n0 = bx*64, m0 = by*64;
    if (z == 0){ emb = enc_emb; W = Wih_f;  bias = b_f;   C = g_xw_f; ldb = 128; ldc = 1024; }
    else if (z == 1){ emb = enc_emb; W = Wih_b; bias = b_b; C = g_xw_b; ldb = 128; ldc = 1024; }
    else { emb = dec_emb; W = dec_Wih; bias = dec_b; C = g_xg; ldb = 640; ldc = 2048; }

    if (tid < 64){
        int m = m0 + tid;
        toks[tid] = (z == 2) ? trg[(m & 127)*128 + (m >> 7)]
                             : src[(m & 127)*512 + (m >> 7)];
    }
    __syncthreads();

    const int tx = tid & 15, ty = tid >> 4;
    ull acc[4][2];
#pragma unroll
    for (int i=0;i<4;i++){ acc[i][0]=fdup(0.f); acc[i][1]=fdup(0.f); }

    for (int k0 = 0; k0 < 128; k0 += 16){
#pragma unroll 4
        for (int i = tid; i < 1024; i += 256){
            int mm = i >> 4, kk = i & 15;
            As[kk][mm] = emb[(size_t)toks[mm]*128 + k0 + kk];
        }
#pragma unroll 4
        for (int i = tid; i < 1024; i += 256){
            int nn = i >> 4, kk = i & 15;
            Bs[kk][nn] = W[(size_t)(n0+nn)*ldb + k0 + kk];
        }
        __syncthreads();
#pragma unroll
        for (int kk = 0; kk < 16; kk++){
            ull a2[4], b2[2];
#pragma unroll
            for (int i=0;i<4;i++) a2[i] = fdup(As[kk][ty + 16*i]);
            b2[0] = *(const ull*)&Bs[kk][2*tx];
            b2[1] = *(const ull*)&Bs[kk][2*tx + 32];
#pragma unroll
            for (int i=0;i<4;i++){
                fma2(acc[i][0], a2[i], b2[0]);
                fma2(acc[i][1], a2[i], b2[1]);
            }
        }
        __syncthreads();
    }
#pragma unroll
    for (int i=0;i<4;i++){
        int m = m0 + ty + 16*i;
#pragma unroll
        for (int jp=0;jp<2;jp++){
            int n = n0 + 2*tx + 32*jp;
            float2 v = upk(acc[i][jp]);
            v.x += bias[n]; v.y += bias[n+1];
            *(float2*)&C[(size_t)m*ldc + n] = v;
        }
    }
}

// ------------------------- enc_proj GEMM (bf16 A, bf16 out) ------------------
__global__ void __launch_bounds__(256)
sgemm_proj(const float* __restrict__ Bw, const float* __restrict__ bias)
{
    __shared__ float As[16][65];
    __shared__ __align__(8) float Bs[16][66];
    const int n0 = blockIdx.x * 64;
    const int m0 = blockIdx.y * 64;
    const int tid = threadIdx.x;
    const int tx = tid & 15, ty = tid >> 4;
    const __nv_bfloat16* A = (const __nv_bfloat16*)g_encout_bf;
    ull acc[4][2];
#pragma unroll
    for (int i=0;i<4;i++){ acc[i][0]=fdup(0.f); acc[i][1]=fdup(0.f); }

    for (int k0 = 0; k0 < 512; k0 += 16){
#pragma unroll 4
        for (int i = tid; i < 1024; i += 256){
            int mm = i >> 4, kk = i & 15;
            As[kk][mm] = __bfloat162float(A[(size_t)(m0+mm)*512 + k0 + kk]);
        }
#pragma unroll 4
        for (int i = tid; i < 1024; i += 256){
            int kk = i >> 6, nn = i & 63;
            Bs[kk][nn] = Bw[(size_t)(k0+kk)*512 + n0 + nn];
        }
        __syncthreads();
#pragma unroll
        for (int kk = 0; kk < 16; kk++){
            ull a2[4], b2[2];
#pragma unroll
            for (int i=0;i<4;i++) a2[i] = fdup(As[kk][ty + 16*i]);
            b2[0] = *(const ull*)&Bs[kk][2*tx];
            b2[1] = *(const ull*)&Bs[kk][2*tx + 32];
#pragma unroll
            for (int i=0;i<4;i++){
                fma2(acc[i][0], a2[i], b2[0]);
                fma2(acc[i][1], a2[i], b2[1]);
            }
        }
        __syncthreads();
    }
    __nv_bfloat16* Cb = (__nv_bfloat16*)g_encproj;
#pragma unroll
    for (int i=0;i<4;i++){
        int m = m0 + ty + 16*i;
#pragma unroll
        for (int jp=0;jp<2;jp++){
            int n = n0 + 2*tx + 32*jp;
            float2 v = upk(acc[i][jp]);
            v.x += bias[n]; v.y += bias[n+1];
            *(__nv_bfloat162*)&Cb[(size_t)m*512 + n] = __float22bfloat162_rn(v);
        }
    }
}

// ------------------------- persistent encoder --------------------------------
__global__ void __launch_bounds__(256) __cluster_dims__(8, 1, 1)
k_encoder(const float* __restrict__ Whh_f, const float* __restrict__ Whh_b)
{
    extern __shared__ float ws[];            // 256*132 floats
    __shared__ float hsf[256*18];
    const int bx  = blockIdx.x;
    const int jt  = bx & 7, bt = (bx >> 3) & 7, dir = bx >> 6;
    const int j0  = jt*32, b0 = bt*16;
    const int tid = threadIdx.x;
    const int tx  = tid & 31;
    const int ty  = tid >> 5;
    const float* __restrict__ Whh = dir ? Whh_b : Whh_f;
    const float* __restrict__ xw  = dir ? g_xw_b : g_xw_f;

#pragma unroll 4
    for (int i = tid; i < 32768; i += 256){
        int k = i & 255, nl = i >> 8;
        int jj = nl >> 2, g = nl & 3;
        ws[k*132 + nl] = Whh[(size_t)(g*256 + j0 + jj)*256 + k];
    }
    __syncthreads();

    float cr[2] = {0.f, 0.f};
    const int j = j0 + tx;

    for (int s = 0; s < 512; s++){
        const int sa = dir ? (511 - s) : s;
        const float* __restrict__ hin = g_h_enc[s & 1][dir];
        float* __restrict__ hout      = g_h_enc[(s & 1) ^ 1][dir];

#pragma unroll
        for (int i = tid; i < 4096; i += 256){
            int b = i >> 8, k = i & 255;
            hsf[k*18 + b] = __ldcg(&hin[(b0 + b)*256 + k]);
        }
        __syncthreads();

        ull accA[2], accB[2];
        accA[0]=fdup(0.f); accA[1]=fdup(0.f);
        accB[0]=fdup(0.f); accB[1]=fdup(0.f);

#pragma unroll 16
        for (int k = 0; k < 256; k++){
            const ull* wp = (const ull*)(ws + k*132 + 4*tx);
            ull w01 = wp[0], w23 = wp[1];
            float2 hp = *(const float2*)(hsf + k*18 + 2*ty);
            ull hd0 = fdup(hp.x), hd1 = fdup(hp.y);
            fma2(accA[0], w01, hd0);
            fma2(accB[0], w23, hd0);
            fma2(accA[1], w01, hd1);
            fma2(accB[1], w23, hd1);
        }
        __syncthreads();

#pragma unroll
        for (int r = 0; r < 2; r++){
            int b = b0 + 2*ty + r;
            float2 g01 = upk(accA[r]);
            float2 g23 = upk(accB[r]);
            const float* xwb = xw + ((size_t)sa*128 + b)*1024 + j;
            float ig = fsig (g01.x + xwb[0]);
            float fg = fsig (g01.y + xwb[256]);
            float gg = ftanh(g23.x + xwb[512]);
            float og = fsig (g23.y + xwb[768]);
            float cn = fmaf(fg, cr[r], ig*gg);
            cr[r] = cn;
            float hn = og * ftanh(cn);
            hout[b*256 + j] = hn;
            ((__nv_bfloat16*)g_encout_bf)[((size_t)b*512 + sa)*512 + dir*256 + j]
                = __float2bfloat16(hn);
        }
        if (s < 511){
            CLUSTER_SYNC();
        } else {
#pragma unroll
            for (int r = 0; r < 2; r++)
                g_c_enc[dir][(b0 + 2*ty + r)*256 + j] = cr[r];
        }
    }
}

// =============== decoder phase GEMMs: 128m x 16n, m-paired f32x2 ==============
// 512 threads: kh = tid>>8 (K half), r = tid&255: mg = r>>4 (8 m-rows), nn = r&15.
// smem layout within sm[]: As [2][16][136] @0 (4352), Bsh [2][16][16] @4352 (512),
// ps [128][17] @4864 (2176). Total 7040 floats.

// ---- phase A: C[128, n0+16] = A(128,K) @ B(K-major) (+bias) ----
__device__ void gmA(float* sm, const float* __restrict__ A, int lda,
                    const float* __restrict__ B, int ldb, int K,
                    int n0, const float* __restrict__ bias,
                    float* __restrict__ C, int ldc)
{
    float* As  = sm;
    float* Bsh = sm + 4352;
    float* ps  = sm + 4864;
    const int tid = threadIdx.x;
    const int kh = tid >> 8, r = tid & 255;
    const int mg = r >> 4, nn = r & 15;
    const int khb = kh * 16;
    const int kbase = kh * (K >> 1);
    const int ntile = K >> 5;
    const int lm = r >> 1, lkq = (r & 1) * 8;
    const int lbk = r >> 4, lbn = r & 15;

    ull acc[4];
#pragma unroll
    for (int i = 0; i < 4; i++) acc[i] = fdup(0.f);

    float4 ra0, ra1; float rb;
    {
        int k0 = kbase;
        ra0 = *(const float4*)&A[(size_t)lm*lda + k0 + lkq];
        ra1 = *(const float4*)&A[(size_t)lm*lda + k0 + lkq + 4];
        rb  = B[(size_t)(k0 + lbk)*ldb + n0 + lbn];
    }
    for (int it = 0; it < ntile; it++){
        {
            float* a = As + (khb + lkq)*136 + lm;
            a[0]     = ra0.x; a[136]   = ra0.y; a[272]   = ra0.z; a[408]   = ra0.w;
            a[544]   = ra1.x; a[680]   = ra1.y; a[816]   = ra1.z; a[952]   = ra1.w;
        }
        Bsh[(khb + lbk)*16 + lbn] = rb;
        __syncthreads();
        if (it + 1 < ntile){
            int k0 = kbase + (it + 1)*16;
            ra0 = *(const float4*)&A[(size_t)lm*lda + k0 + lkq];
            ra1 = *(const float4*)&A[(size_t)lm*lda + k0 + lkq + 4];
            rb  = B[(size_t)(k0 + lbk)*ldb + n0 + lbn];
        }
#pragma unroll
        for (int kk = 0; kk < 16; kk++){
            ull b2 = fdup(Bsh[(khb + kk)*16 + nn]);
            const ull* ap = (const ull*)(As + (khb + kk)*136 + 8*mg);
            fma2(acc[0], ap[0], b2);
            fma2(acc[1], ap[1], b2);
            fma2(acc[2], ap[2], b2);
            fma2(acc[3], ap[3], b2);
        }
        __syncthreads();
    }
    if (kh == 1){
#pragma unroll
        for (int i = 0; i < 4; i++){
            float2 v = upk(acc[i]);
            ps[(8*mg + 2*i)*17 + nn]     = v.x;
            ps[(8*mg + 2*i + 1)*17 + nn] = v.y;
        }
    }
    __syncthreads();
    if (kh == 0){
        float bv = bias ? bias[n0 + nn] : 0.f;
#pragma unroll
        for (int i = 0; i < 4; i++){
            float2 v = upk(acc[i]);
            int m = 8*mg + 2*i;
            C[(size_t)m*ldc + n0 + nn]     = v.x + ps[m*17 + nn] + bv;
            C[(size_t)(m+1)*ldc + n0 + nn] = v.y + ps[(m+1)*17 + nn] + bv;
        }
    }
    __syncthreads();
}

// ---- phase C: gates(128m x 16n) over [ctx|h] @ wcat^T, fused LSTM cell ----
// block covers cells j0..j0+3 (x4 gates); n index nn = g*4 + jj.
__device__ void gmC(float* sm, int j0, int t, float& cr)
{
    float* As  = sm;
    float* Bsh = sm + 4352;
    float* ps  = sm + 4864;
    const int tid = threadIdx.x;
    const int kh = tid >> 8, r = tid & 255;
    const int mg = r >> 4, nn = r & 15;
    const int khb = kh * 16;
    const int kbase = kh * 512;
    const int lm = r >> 1, lkq = (r & 1) * 8;
    const int lbn = r >> 4, lbk = r & 15;
    const int lrow = (lbn >> 2)*512 + j0 + (lbn & 3);

    ull acc[4];
#pragma unroll
    for (int i = 0; i < 4; i++) acc[i] = fdup(0.f);

    float4 ra0, ra1; float rb;
    {
        int k0 = kbase;
        ra0 = *(const float4*)&g_u[lm*1024 + k0 + lkq];
        ra1 = *(const float4*)&g_u[lm*1024 + k0 + lkq + 4];
        rb  = g_wcat[(size_t)lrow*1024 + k0 + lbk];
    }
    for (int it = 0; it < 32; it++){
        {
            float* a = As + (khb + lkq)*136 + lm;
            a[0]     = ra0.x; a[136]   = ra0.y; a[272]   = ra0.z; a[408]   = ra0.w;
            a[544]   = ra1.x; a[680]   = ra1.y; a[816]   = ra1.z; a[952]   = ra1.w;
        }
        Bsh[(khb + lbk)*16 + lbn] = rb;
        __syncthreads();
        if (it + 1 < 32){
            int k0 = kbase + (it + 1)*16;
            ra0 = *(const float4*)&g_u[lm*1024 + k0 + lkq];
            ra1 = *(const float4*)&g_u[lm*1024 + k0 + lkq + 4];
            rb  = g_wcat[(size_t)lrow*1024 + k0 + lbk];
        }
#pragma unroll
        for (int kk = 0; kk < 16; kk++){
            ull b2 = fdup(Bsh[(khb + kk)*16 + nn]);
            const ull* ap = (const ull*)(As + (khb + kk)*136 + 8*mg);
            fma2(acc[0], ap[0], b2);
            fma2(acc[1], ap[1], b2);
            fma2(acc[2], ap[2], b2);
            fma2(acc[3], ap[3], b2);
        }
        __syncthreads();
    }
    // reduce K-halves into ps[m][nn]
    if (kh == 1){
#pragma unroll
        for (int i = 0; i < 4; i++){
            float2 v = upk(acc[i]);
            ps[(8*mg + 2*i)*17 + nn]     = v.x;
            ps[(8*mg + 2*i + 1)*17 + nn] = v.y;
        }
    }
    __syncthreads();
    if (kh == 0){
#pragma unroll
        for (int i = 0; i < 4; i++){
            float2 v = upk(acc[i]);
            int m = 8*mg + 2*i;
            ps[m*17 + nn]     += v.x;
            ps[(m+1)*17 + nn] += v.y;
        }
    }
    __syncthreads();
    // LSTM cell: thread -> (m = tid&127, jj = tid>>7), j = j0+jj
    {
        const int me = tid & 127, jj = tid >> 7;
        const int j = j0 + jj;
        const float* xgb = g_xg + (size_t)t*BB*2048 + (size_t)me*2048;
        float ig = fsig (ps[me*17 + jj]      + xgb[j]);
        float fg = fsig (ps[me*17 + 4 + jj]  + xgb[512  + j]);
        float gg = ftanh(ps[me*17 + 8 + jj]  + xgb[1024 + j]);
        float og = fsig (ps[me*17 + 12 + jj] + xgb[1536 + j]);
        float cn = fmaf(fg, cr, ig*gg);
        cr = cn;
        g_u[me*1024 + 512 + j] = og * ftanh(cn);
    }
    __syncthreads();
}

// ------------------------- decoder attention (bf16x2 tanh + L2 steering) -----
__device__ __forceinline__ float dot16b(ulonglong4 u, const uint32_t* q2,
                                        const float* av, float acc){
    const uint32_t* w = (const uint32_t*)&u;
#pragma unroll
    for (int p = 0; p < 8; p++){
        uint32_t s = tanh2b(hadd2b(w[p], q2[p]));
        float lo = __uint_as_float(s << 16);
        float hi = __uint_as_float(s & 0xFFFF0000u);
        acc = fmaf(av[2*p],     lo, acc);
        acc = fmaf(av[2*p + 1], hi, acc);
    }
    return acc;
}

__device__ void attention(float* sm, int b, const float* __restrict__ attn_v)
{
    float* qsh   = sm;            // 512
    float* sc    = sm + 512;      // 512
    float* red   = sm + 1024;     // 16
    float* partc = sm + 1040;     // 16*512
    const int tid = threadIdx.x, lane = tid & 31, warp = tid >> 5;

    qsh[tid] = __ldcg(&g_q[b*512 + tid]);
    __syncthreads();

    uint32_t qv2[8];
    float av[16];
#pragma unroll
    for (int i = 0; i < 8; i++){
        float lo = qsh[16*lane + 2*i], hi = qsh[16*lane + 2*i + 1];
        qv2[i] = packbf2(lo, hi);
    }
#pragma unroll
    for (int i = 0; i < 16; i++) av[i] = attn_v[16*lane + i];

    const char* __restrict__ prb = (const char*)(g_encproj + (size_t)b*512*256);
    ulonglong4 c0, c1;
    {
        int s0 = warp, s1 = warp + 256;
        c0 = ldg_el64(prb + s0*1024 + lane*32);
        c1 = ldg_el64(prb + s1*1024 + lane*32);
    }
    for (int i = 0; i < 16; i++){
        ulonglong4 n0, n1;
        if (i < 15){
            int s0 = warp + 16*(i+1), s1 = s0 + 256;
            n0 = ldg_el64(prb + s0*1024 + lane*32);
            n1 = ldg_el64(prb + s1*1024 + lane*32);
        }
        float a0 = dot16b(c0, qv2, av, 0.f);
        float a1 = dot16b(c1, qv2, av, 0.f);
#pragma unroll
        for (int o = 16; o; o >>= 1){
            a0 += __shfl_xor_sync(~0u, a0, o);
            a1 += __shfl_xor_sync(~0u, a1, o);
        }
        if (lane == 0){ sc[warp + 16*i] = a0; sc[warp + 16*i + 256] = a1; }
        c0 = n0; c1 = n1;
    }
    __syncthreads();

    float v = sc[tid];
    float m = v;
#pragma unroll
    for (int o = 16; o; o >>= 1) m = fmaxf(m, __shfl_xor_sync(~0u, m, o));
    if (lane == 0) red[warp] = m;
    __syncthreads();
    m = red[0];
#pragma unroll
    for (int i = 1; i < 16; i++) m = fmaxf(m, red[i]);
    __syncthreads();
    float ex = __expf(v - m);
    float ssum = ex;
#pragma unroll
    for (int o = 16; o; o >>= 1) ssum += __shfl_xor_sync(~0u, ssum, o);
    if (lane == 0) red[warp] = ssum;
    __syncthreads();
    ssum = 0.f;
#pragma unroll
    for (int i = 0; i < 16; i++) ssum += red[i];
    sc[tid] = ex * __fdividef(1.f, ssum);
    __syncthreads();

    const char* __restrict__ eob = (const char*)(g_encout_bf + (size_t)b*512*256);
    const int sg = tid >> 5, ec = tid & 31;
    float a[16];
#pragma unroll
    for (int k = 0; k < 16; k++) a[k] = 0.f;
#pragma unroll 8
    for (int i = 0; i < 32; i++){
        int s = sg*32 + i;
        float w = sc[s];
        ulonglong4 u = ldg_ef64(eob + (size_t)s*1024 + ec*32);
        const uint32_t* ww = (const uint32_t*)&u;
#pragma unroll
        for (int p = 0; p < 8; p++){
            float2 f = __bfloat1622float2(*(__nv_bfloat162*)&ww[p]);
            a[2*p]     = fmaf(w, f.x, a[2*p]);
            a[2*p + 1] = fmaf(w, f.y, a[2*p + 1]);
        }
    }
#pragma unroll
    for (int k = 0; k < 16; k += 4)
        *(float4*)&partc[sg*512 + ec*16 + k] = *(float4*)&a[k];
    __syncthreads();
    {
        float r = 0.f;
#pragma unroll
        for (int g = 0; g < 16; g++) r += partc[g*512 + tid];
        g_u[b*1024 + tid] = r;
    }
    __syncthreads();
}

// ------------------------- persistent decoder --------------------------------
__global__ void __launch_bounds__(512)
k_decoder(const float* __restrict__ attn_W, const float* __restrict__ attn_v,
          const float* __restrict__ out_W, const float* __restrict__ out_b,
          float* __restrict__ out)
{
    __shared__ __align__(16) float sm[9248];
    const int bid = blockIdx.x, tid = threadIdx.x;
    const int j0 = bid * 4;
    unsigned tgt = g_bar_epoch;

    float cr;
    {
        const int me = tid & 127, jj = tid >> 7;
        const int j = j0 + jj;
        float h;
        if (j < 256){ h = g_h_enc[0][0][me*256 + j];       cr = g_c_enc[0][me*256 + j]; }
        else        { h = g_h_enc[0][1][me*256 + j - 256]; cr = g_c_enc[1][me*256 + j - 256]; }
        g_u[me*1024 + 512 + j] = h;
    }
    tgt++; dbar(tgt);

    for (int t = 0; t < TT; t++){
        if (bid < 32){
            gmA(sm, g_u + 512, 1024, attn_W, 512, 512,
                bid*16, nullptr, g_q, 512);
        } else if (bid < 40 && t > 0){
            gmA(sm, g_u + 512, 1024, out_W, 128, 512,
                (bid - 32)*16, out_b, out + (size_t)t*128, 16384);
        }
        tgt++; dbar(tgt);
        attention(sm, bid, attn_v);
        tgt++; dbar(tgt);
        gmC(sm, j0, t, cr);
        tgt++; dbar(tgt);
    }
    if (bid < 8){
        gmA(sm, g_u + 512, 1024, out_W, 128, 512,
            bid*16, out_b, out + (size_t)TT*128, 16384);
    }
}

// ------------------------- launch --------------------------------------------
extern "C" void kernel_launch(void* const* d_in, const int* in_sizes, int n_in,
                              void* d_out, int out_size)
{
    const int*   src     = (const int*)  d_in[0];
    const int*   trg     = (const int*)  d_in[1];
    const float* enc_emb = (const float*)d_in[2];
    const float* Wih_f   = (const float*)d_in[3];
    const float* Whh_f   = (const float*)d_in[4];
    const float* b_f     = (const float*)d_in[5];
    const float* Wih_b   = (const float*)d_in[6];
    const float* Whh_b   = (const float*)d_in[7];
    const float* b_b     = (const float*)d_in[8];
    const float* dec_emb = (const float*)d_in[9];
    const float* dec_Wih = (const float*)d_in[10];
    const float* dec_Whh = (const float*)d_in[11];
    const float* dec_b   = (const float*)d_in[12];
    const float* attn_W  = (const float*)d_in[13];
    const float* attn_b  = (const float*)d_in[14];
    const float* attn_v  = (const float*)d_in[15];
    const float* out_W   = (const float*)d_in[16];
    const float* out_b   = (const float*)d_in[17];
    float* out = (float*)d_out;

    cudaFuncSetAttribute(k_encoder,
        cudaFuncAttributeMaxDynamicSharedMemorySize, 256*132*4);

    // 1) fused prep + input-gate GEMMs
    k_pre<<<dim3(32, 1024, 3), 256>>>(src, trg, enc_emb, dec_emb,
                                      Wih_f, b_f, Wih_b, b_b,
                                      dec_Wih, dec_Whh, dec_b, out);
    // 2) persistent encoder
    k_encoder<<<128, 256, 256*132*4>>>(Whh_f, Whh_b);
    // 3) enc_proj = enc_out(bf16) @ We + attn_b -> bf16
    sgemm_proj<<<dim3(512/64, (BB*SS)/64), 256>>>(attn_W + 512*512, attn_b);
    // 4) persistent decoder
    k_decoder<<<128, 512>>>(attn_W, attn_v, out_W, out_b, out);
}

// round 16
// speedup vs baseline: 1.3039x; 1.0756x over previous
#include <cuda_runtime.h>
#include <cuda_bf16.h>
#include <cstdint>
#include <cstddef>

#define BB  128
#define SS  512
#define EE  128
#define HH  256
#define HD  512
#define TT  127

typedef unsigned long long ull;

// ------------------------- device scratch ------------------------------------
__device__ float g_xw_f[(size_t)SS*BB*4*HH];
__device__ float g_xw_b[(size_t)SS*BB*4*HH];
__device__ float g_h_enc[2][2][BB*HH];                 // [parity][dir]
__device__ float g_c_enc[2][BB*HH];                    // final cells [dir]
__device__ __nv_bfloat162 g_encout_bf[(size_t)BB*SS*256]; // (b,s,512) bf16
__device__ __nv_bfloat162 g_encproj[(size_t)BB*SS*256];   // bf16 + attn_b
__device__ float g_xg[(size_t)TT*BB*4*HD];
__device__ float g_wcat[(size_t)4*HD*1024];            // [Wih_ctx | Whh]
__device__ float g_u[BB*1024];                         // [ctx(512) | h(512)]

// barrier state: per-block flag slots on separate 256B lines; no atomics.
__device__ volatile unsigned g_flag[128*64];
__device__ volatile unsigned g_dgen[64];
__device__ unsigned g_bar_epoch;

// ------------------------- math helpers --------------------------------------
__device__ __forceinline__ float ftanh(float x){
    float e = __expf(2.f*x);
    return 1.f - __fdividef(2.f, e + 1.f);
}
__device__ __forceinline__ float fsig(float x){
    return __fdividef(1.f, 1.f + __expf(-x));
}
__device__ __forceinline__ ull fdup(float x){
    ull r; asm("mov.b64 %0, {%1, %1};" : "=l"(r) : "f"(x)); return r;
}
__device__ __forceinline__ ull fpack(float lo, float hi){
    ull r; asm("mov.b64 %0, {%1, %2};" : "=l"(r) : "f"(lo), "f"(hi)); return r;
}
__device__ __forceinline__ void fma2(ull& d, ull a, ull b){
    asm("fma.rn.f32x2 %0, %1, %2, %0;" : "+l"(d) : "l"(a), "l"(b));
}
__device__ __forceinline__ float2 upk(ull v){
    float2 f; asm("mov.b64 {%0, %1}, %2;" : "=f"(f.x), "=f"(f.y) : "l"(v));
    return f;
}
// bf16x2 ops for the score pass
__device__ __forceinline__ uint32_t hadd2b(uint32_t a, uint32_t b){
    uint32_t r; asm("add.rn.bf16x2 %0, %1, %2;" : "=r"(r) : "r"(a), "r"(b));
    return r;
}
__device__ __forceinline__ uint32_t tanh2b(uint32_t a){
    uint32_t r; asm("tanh.approx.bf16x2 %0, %1;" : "=r"(r) : "r"(a));
    return r;
}
__device__ __forceinline__ uint32_t packbf2(float lo, float hi){
    uint32_t r; asm("cvt.rn.bf16x2.f32 %0, %1, %2;" : "=r"(r) : "f"(hi), "f"(lo));
    return r;
}
// L2 cache-steered 256-bit loads (sm_103a requires v4.b64 for evict policy)
__device__ __forceinline__ ulonglong4 ldg_el64(const void* p){
    ulonglong4 u;
    asm volatile("ld.global.nc.L2::evict_last.v4.u64 {%0,%1,%2,%3}, [%4];"
                 : "=l"(u.x), "=l"(u.y), "=l"(u.z), "=l"(u.w) : "l"(p));
    return u;
}
__device__ __forceinline__ ulonglong4 ldg_ef64(const void* p){
    ulonglong4 u;
    asm volatile("ld.global.nc.L2::evict_first.v4.u64 {%0,%1,%2,%3}, [%4];"
                 : "=l"(u.x), "=l"(u.y), "=l"(u.z), "=l"(u.w) : "l"(p));
    return u;
}

// flag barrier (replay-safe monotonic targets)
__device__ __forceinline__ void dbar(unsigned tgt){
    __threadfence();
    __syncthreads();
    if (threadIdx.x == 0) g_flag[blockIdx.x << 6] = tgt;
    if (blockIdx.x == 0 && threadIdx.x < 32){
        for (;;){
            bool ok = true;
#pragma unroll
            for (int i = 0; i < 4; i++)
                ok &= ((unsigned)(g_flag[(threadIdx.x*4 + i) << 6] - tgt) < 0x80000000u);
            if (__all_sync(0xffffffffu, ok)) break;
        }
        if (threadIdx.x == 0){ __threadfence(); g_dgen[0] = tgt; }
    }
    if (threadIdx.x == 0){
        while ((unsigned)(g_dgen[0] - tgt) >= 0x80000000u) __nanosleep(32);
        __threadfence();
    }
    __syncthreads();
}

#define CLUSTER_SYNC() do { \
    asm volatile("barrier.cluster.arrive.aligned;" ::: "memory"); \
    asm volatile("barrier.cluster.wait.aligned;"   ::: "memory"); \
} while(0)

// ------------------------- k_pre: fused gather-GEMMs + pack + init -----------
__global__ void __launch_bounds__(256)
k_pre(const int* __restrict__ src, const int* __restrict__ trg,
      const float* __restrict__ enc_emb, const float* __restrict__ dec_emb,
      const float* __restrict__ Wih_f, const float* __restrict__ b_f,
      const float* __restrict__ Wih_b, const float* __restrict__ b_b,
      const float* __restrict__ dec_Wih, const float* __restrict__ dec_Whh,
      const float* __restrict__ dec_b, float* __restrict__ out)
{
    const int z = blockIdx.z, bx = blockIdx.x, by = blockIdx.y;
    const int tid = threadIdx.x;

    if (z == 2 && by >= 254){
        size_t idx = ((size_t)(by - 254)*32 + bx)*256 + tid;
        if (idx < (size_t)2048*1024){
            int n = idx >> 10, k = idx & 1023;
            g_wcat[idx] = (k < 512) ? dec_Wih[(size_t)n*640 + 128 + k]
                                    : dec_Whh[(size_t)n*512 + k - 512];
        } else if (idx < 2097152 + 65536){
            (&g_h_enc[0][0][0])[idx - 2097152] = 0.f;
        } else if (idx < 2162688 + 16384){
            size_t i3 = idx - 2162688;
            out[(i3 >> 7)*16384 + (i3 & 127)] = 0.f;
        } else if (idx == 2179072){
            g_bar_epoch += 4096u;
        }
        return;
    }
    if (z != 2 && bx >= 16) return;

    __shared__ int   toks[64];
    __shared__ float As[16][65];
    __shared__ __align__(8) float Bs[16][66];

    const float* emb;
    const float* W; const float* bias; float* C;
    int ldb, ldc, n0 = bx*64, m0 = by*64;
    if (z == 0){ emb = enc_emb; W = Wih_f;  bias = b_f;   C = g_xw_f; ldb = 128; ldc = 1024; }
    else if (z == 1){ emb = enc_emb; W = Wih_b; bias = b_b; C = g_xw_b; ldb = 128; ldc = 1024; }
    else { emb = dec_emb; W = dec_Wih; bias = dec_b; C = g_xg; ldb = 640; ldc = 2048; }

    if (tid < 64){
        int m = m0 + tid;
        toks[tid] = (z == 2) ? trg[(m & 127)*128 + (m >> 7)]
                             : src[(m & 127)*512 + (m >> 7)];
    }
    __syncthreads();

    const int tx = tid & 15, ty = tid >> 4;
    ull acc[4][2];
#pragma unroll
    for (int i=0;i<4;i++){ acc[i][0]=fdup(0.f); acc[i][1]=fdup(0.f); }

    for (int k0 = 0; k0 < 128; k0 += 16){
#pragma unroll 4
        for (int i = tid; i < 1024; i += 256){
            int mm = i >> 4, kk = i & 15;
            As[kk][mm] = emb[(size_t)toks[mm]*128 + k0 + kk];
        }
#pragma unroll 4
        for (int i = tid; i < 1024; i += 256){
            int nn = i >> 4, kk = i & 15;
            Bs[kk][nn] = W[(size_t)(n0+nn)*ldb + k0 + kk];
        }
        __syncthreads();
#pragma unroll
        for (int kk = 0; kk < 16; kk++){
            ull a2[4], b2[2];
#pragma unroll
            for (int i=0;i<4;i++) a2[i] = fdup(As[kk][ty + 16*i]);
            b2[0] = *(const ull*)&Bs[kk][2*tx];
            b2[1] = *(const ull*)&Bs[kk][2*tx + 32];
#pragma unroll
            for (int i=0;i<4;i++){
                fma2(acc[i][0], a2[i], b2[0]);
                fma2(acc[i][1], a2[i], b2[1]);
            }
        }
        __syncthreads();
    }
#pragma unroll
    for (int i=0;i<4;i++){
        int m = m0 + ty + 16*i;
#pragma unroll
        for (int jp=0;jp<2;jp++){
            int n = n0 + 2*tx + 32*jp;
            float2 v = upk(acc[i][jp]);
            v.x += bias[n]; v.y += bias[n+1];
            *(float2*)&C[(size_t)m*ldc + n] = v;
        }
    }
}

// ------------------------- enc_proj GEMM (bf16 A, bf16 out) ------------------
__global__ void __launch_bounds__(256)
sgemm_proj(const float* __restrict__ Bw, const float* __restrict__ bias)
{
    __shared__ float As[16][65];
    __shared__ __align__(8) float Bs[16][66];
    const int n0 = blockIdx.x * 64;
    const int m0 = blockIdx.y * 64;
    const int tid = threadIdx.x;
    const int tx = tid & 15, ty = tid >> 4;
    const __nv_bfloat16* A = (const __nv_bfloat16*)g_encout_bf;
    ull acc[4][2];
#pragma unroll
    for (int i=0;i<4;i++){ acc[i][0]=fdup(0.f); acc[i][1]=fdup(0.f); }

    for (int k0 = 0; k0 < 512; k0 += 16){
#pragma unroll 4
        for (int i = tid; i < 1024; i += 256){
            int mm = i >> 4, kk = i & 15;
            As[kk][mm] = __bfloat162float(A[(size_t)(m0+mm)*512 + k0 + kk]);
        }
#pragma unroll 4
        for (int i = tid; i < 1024; i += 256){
            int kk = i >> 6, nn = i & 63;
            Bs[kk][nn] = Bw[(size_t)(k0+kk)*512 + n0 + nn];
        }
        __syncthreads();
#pragma unroll
        for (int kk = 0; kk < 16; kk++){
            ull a2[4], b2[2];
#pragma unroll
            for (int i=0;i<4;i++) a2[i] = fdup(As[kk][ty + 16*i]);
            b2[0] = *(const ull*)&Bs[kk][2*tx];
            b2[1] = *(const ull*)&Bs[kk][2*tx + 32];
#pragma unroll
            for (int i=0;i<4;i++){
                fma2(acc[i][0], a2[i], b2[0]);
                fma2(acc[i][1], a2[i], b2[1]);
            }
        }
        __syncthreads();
    }
    __nv_bfloat16* Cb = (__nv_bfloat16*)g_encproj;
#pragma unroll
    for (int i=0;i<4;i++){
        int m = m0 + ty + 16*i;
#pragma unroll
        for (int jp=0;jp<2;jp++){
            int n = n0 + 2*tx + 32*jp;
            float2 v = upk(acc[i][jp]);
            v.x += bias[n]; v.y += bias[n+1];
            *(__nv_bfloat162*)&Cb[(size_t)m*512 + n] = __float22bfloat162_rn(v);
        }
    }
}

// ------------------------- persistent encoder --------------------------------
__global__ void __launch_bounds__(256) __cluster_dims__(8, 1, 1)
k_encoder(const float* __restrict__ Whh_f, const float* __restrict__ Whh_b)
{
    extern __shared__ float ws[];            // 256*132 floats
    __shared__ float hsf[256*18];
    const int bx  = blockIdx.x;
    const int jt  = bx & 7, bt = (bx >> 3) & 7, dir = bx >> 6;
    const int j0  = jt*32, b0 = bt*16;
    const int tid = threadIdx.x;
    const int tx  = tid & 31;
    const int ty  = tid >> 5;
    const float* __restrict__ Whh = dir ? Whh_b : Whh_f;
    const float* __restrict__ xw  = dir ? g_xw_b : g_xw_f;

#pragma unroll 4
    for (int i = tid; i < 32768; i += 256){
        int k = i & 255, nl = i >> 8;
        int jj = nl >> 2, g = nl & 3;
        ws[k*132 + nl] = Whh[(size_t)(g*256 + j0 + jj)*256 + k];
    }
    __syncthreads();

    float cr[2] = {0.f, 0.f};
    const int j = j0 + tx;

    for (int s = 0; s < 512; s++){
        const int sa = dir ? (511 - s) : s;
        const float* __restrict__ hin = g_h_enc[s & 1][dir];
        float* __restrict__ hout      = g_h_enc[(s & 1) ^ 1][dir];

#pragma unroll
        for (int i = tid; i < 4096; i += 256){
            int b = i >> 8, k = i & 255;
            hsf[k*18 + b] = __ldcg(&hin[(b0 + b)*256 + k]);
        }
        __syncthreads();

        ull accA[2], accB[2];
        accA[0]=fdup(0.f); accA[1]=fdup(0.f);
        accB[0]=fdup(0.f); accB[1]=fdup(0.f);

#pragma unroll 16
        for (int k = 0; k < 256; k++){
            const ull* wp = (const ull*)(ws + k*132 + 4*tx);
            ull w01 = wp[0], w23 = wp[1];
            float2 hp = *(const float2*)(hsf + k*18 + 2*ty);
            ull hd0 = fdup(hp.x), hd1 = fdup(hp.y);
            fma2(accA[0], w01, hd0);
            fma2(accB[0], w23, hd0);
            fma2(accA[1], w01, hd1);
            fma2(accB[1], w23, hd1);
        }
        __syncthreads();

#pragma unroll
        for (int r = 0; r < 2; r++){
            int b = b0 + 2*ty + r;
            float2 g01 = upk(accA[r]);
            float2 g23 = upk(accB[r]);
            const float* xwb = xw + ((size_t)sa*128 + b)*1024 + j;
            float ig = fsig (g01.x + xwb[0]);
            float fg = fsig (g01.y + xwb[256]);
            float gg = ftanh(g23.x + xwb[512]);
            float og = fsig (g23.y + xwb[768]);
            float cn = fmaf(fg, cr[r], ig*gg);
            cr[r] = cn;
            float hn = og * ftanh(cn);
            hout[b*256 + j] = hn;
            ((__nv_bfloat16*)g_encout_bf)[((size_t)b*512 + sa)*512 + dir*256 + j]
                = __float2bfloat16(hn);
        }
        if (s < 511){
            CLUSTER_SYNC();
        } else {
#pragma unroll
            for (int r = 0; r < 2; r++)
                g_c_enc[dir][(b0 + 2*ty + r)*256 + j] = cr[r];
        }
    }
}

// ------------------------- final-step logits (per block b) -------------------
__device__ void dec_logits(float* sm, int b, int t,
                           const float* __restrict__ out_W,
                           const float* __restrict__ out_b,
                           float* __restrict__ out)
{
    float* hsh = sm;          // 512
    float* ps  = sm + 512;    // 2048
    const int tid = threadIdx.x;
    hsh[tid] = __ldcg(&g_u[b*1024 + 512 + tid]);
    __syncthreads();
    const int ks = tid >> 5, vq = tid & 31;
    ull p01 = fdup(0.f), p23 = fdup(0.f);
    const float* W = out_W + (size_t)(ks*32)*128 + 4*vq;
#pragma unroll 8
    for (int k = 0; k < 32; k++){
        float4 w = *(const float4*)(W + (size_t)k*128);
        ull hd = fdup(hsh[ks*32 + k]);
        fma2(p01, hd, fpack(w.x, w.y));
        fma2(p23, hd, fpack(w.z, w.w));
    }
    float2 a = upk(p01), c = upk(p23);
    float4 st = {a.x, a.y, c.x, c.y};
    *(float4*)&ps[ks*128 + 4*vq] = st;
    __syncthreads();
    if (tid < 128){
        float rsum = out_b[tid];
#pragma unroll
        for (int g = 0; g < 16; g++) rsum += ps[g*128 + tid];
        out[(size_t)b*16384 + t*128 + tid] = rsum;
    }
    __syncthreads();
}

// ------------------------- attention + inline q + inline logits --------------
__device__ __forceinline__ float dot16b(ulonglong4 u, const uint32_t* q2,
                                        const float* av, float acc){
    const uint32_t* w = (const uint32_t*)&u;
#pragma unroll
    for (int p = 0; p < 8; p++){
        uint32_t s = tanh2b(hadd2b(w[p], q2[p]));
        float lo = __uint_as_float(s << 16);
        float hi = __uint_as_float(s & 0xFFFF0000u);
        acc = fmaf(av[2*p],     lo, acc);
        acc = fmaf(av[2*p + 1], hi, acc);
    }
    return acc;
}

__device__ void attention(float* sm, int b, int t,
                          const float* __restrict__ attn_W,
                          const float* __restrict__ attn_v,
                          const float* __restrict__ out_W,
                          const float* __restrict__ out_b,
                          float* __restrict__ out)
{
    float* qsh   = sm;            // 512
    float* sc    = sm + 512;      // 512
    float* red   = sm + 1024;     // 32
    float* hsh   = sm + 1056;     // 512
    float* ps    = sm + 1568;     // 2048 partials (q, then logits)
    float* partc = sm + 3616;     // 16*512 context partials
    const int tid = threadIdx.x, lane = tid & 31, warp = tid >> 5;

    hsh[tid] = __ldcg(&g_u[b*1024 + 512 + tid]);
    __syncthreads();

    // ---- q[b] = h @ Wh (Wh = attn_W[0:512], row-major K x E) ----
    {
        const int kq = tid >> 7, eq = tid & 127;
        ull p01 = fdup(0.f), p23 = fdup(0.f);
        const float* W = attn_W + (size_t)(kq*128)*512 + 4*eq;
#pragma unroll 8
        for (int k = 0; k < 128; k++){
            float4 w = *(const float4*)(W + (size_t)k*512);
            ull hd = fdup(hsh[kq*128 + k]);
            fma2(p01, hd, fpack(w.x, w.y));
            fma2(p23, hd, fpack(w.z, w.w));
        }
        float2 a = upk(p01), c = upk(p23);
        float4 st = {a.x, a.y, c.x, c.y};
        *(float4*)&ps[kq*512 + 4*eq] = st;
    }
    __syncthreads();
    qsh[tid] = ps[tid] + ps[512 + tid] + ps[1024 + tid] + ps[1536 + tid];
    __syncthreads();

    // ---- logits from current h -> out[b, t, :] (t > 0) ----
    if (t > 0){
        const int ks = tid >> 5, vq = tid & 31;
        ull p01 = fdup(0.f), p23 = fdup(0.f);
        const float* W = out_W + (size_t)(ks*32)*128 + 4*vq;
#pragma unroll 8
        for (int k = 0; k < 32; k++){
            float4 w = *(const float4*)(W + (size_t)k*128);
            ull hd = fdup(hsh[ks*32 + k]);
            fma2(p01, hd, fpack(w.x, w.y));
            fma2(p23, hd, fpack(w.z, w.w));
        }
        float2 a = upk(p01), c = upk(p23);
        float4 st = {a.x, a.y, c.x, c.y};
        *(float4*)&ps[ks*128 + 4*vq] = st;
        __syncthreads();
        if (tid < 128){
            float rsum = out_b[tid];
#pragma unroll
            for (int g = 0; g < 16; g++) rsum += ps[g*128 + tid];
            out[(size_t)b*16384 + t*128 + tid] = rsum;
        }
    }

    // per-lane constants for scores
    uint32_t qv2[8];
    float av[16];
#pragma unroll
    for (int i = 0; i < 8; i++){
        float lo = qsh[16*lane + 2*i], hi = qsh[16*lane + 2*i + 1];
        qv2[i] = packbf2(lo, hi);
    }
#pragma unroll
    for (int i = 0; i < 16; i++) av[i] = attn_v[16*lane + i];

    // ---- scores: warp handles rows (warp+16i, warp+16i+256); proj pinned in L2
    const char* __restrict__ prb = (const char*)(g_encproj + (size_t)b*512*256);
    ulonglong4 c0, c1;
    {
        int s0 = warp, s1 = warp + 256;
        c0 = ldg_el64(prb + s0*1024 + lane*32);
        c1 = ldg_el64(prb + s1*1024 + lane*32);
    }
    for (int i = 0; i < 16; i++){
        ulonglong4 n0, n1;
        if (i < 15){
            int s0 = warp + 16*(i+1), s1 = s0 + 256;
            n0 = ldg_el64(prb + s0*1024 + lane*32);
            n1 = ldg_el64(prb + s1*1024 + lane*32);
        }
        float a0 = dot16b(c0, qv2, av, 0.f);
        float a1 = dot16b(c1, qv2, av, 0.f);
#pragma unroll
        for (int o = 16; o; o >>= 1){
            a0 += __shfl_xor_sync(~0u, a0, o);
            a1 += __shfl_xor_sync(~0u, a1, o);
        }
        if (lane == 0){ sc[warp + 16*i] = a0; sc[warp + 16*i + 256] = a1; }
        c0 = n0; c1 = n1;
    }
    __syncthreads();

    // ---- softmax ----
    float v = sc[tid];
    float m = v;
#pragma unroll
    for (int o = 16; o; o >>= 1) m = fmaxf(m, __shfl_xor_sync(~0u, m, o));
    if (lane == 0) red[warp] = m;
    __syncthreads();
    m = red[0];
#pragma unroll
    for (int i = 1; i < 16; i++) m = fmaxf(m, red[i]);
    __syncthreads();
    float ex = __expf(v - m);
    float ssum = ex;
#pragma unroll
    for (int o = 16; o; o >>= 1) ssum += __shfl_xor_sync(~0u, ssum, o);
    if (lane == 0) red[warp] = ssum;
    __syncthreads();
    ssum = 0.f;
#pragma unroll
    for (int i = 0; i < 16; i++) ssum += red[i];
    sc[tid] = ex * __fdividef(1.f, ssum);
    __syncthreads();

    // ---- context: 16 s-groups x 32 e-chunks of 32B; encout streams ----
    const char* __restrict__ eob = (const char*)(g_encout_bf + (size_t)b*512*256);
    const int sg = tid >> 5, ec = tid & 31;
    float a[16];
#pragma unroll
    for (int k = 0; k < 16; k++) a[k] = 0.f;
#pragma unroll 8
    for (int i = 0; i < 32; i++){
        int s = sg*32 + i;
        float w = sc[s];
        ulonglong4 u = ldg_ef64(eob + (size_t)s*1024 + ec*32);
        const uint32_t* ww = (const uint32_t*)&u;
#pragma unroll
        for (int p = 0; p < 8; p++){
            float2 f = __bfloat1622float2(*(__nv_bfloat162*)&ww[p]);
            a[2*p]     = fmaf(w, f.x, a[2*p]);
            a[2*p + 1] = fmaf(w, f.y, a[2*p + 1]);
        }
    }
#pragma unroll
    for (int k = 0; k < 16; k += 4)
        *(float4*)&partc[sg*512 + ec*16 + k] = *(float4*)&a[k];
    __syncthreads();
    {
        float r = 0.f;
#pragma unroll
        for (int g = 0; g < 16; g++) r += partc[g*512 + tid];
        g_u[b*1024 + tid] = r;
    }
    __syncthreads();
}

// ---- phase C: gates(128m x 16n) + fused LSTM cell; double-buffered smem ----
__device__ void gmC(float* sm, int j0, int t, float& cr)
{
    float* As  = sm;            // [2buf][2kh][16][136] = 8704
    float* Bsh = sm + 8704;     // [2buf][2kh][16][16]  = 1024
    float* ps  = sm + 9728;     // 128*17 = 2176
    const int tid = threadIdx.x;
    const int kh = tid >> 8, r = tid & 255;
    const int mg = r >> 4, nn = r & 15;
    const int khb = kh * 16;
    const int kbase = kh * 512;
    const int lm = r >> 1, lkq = (r & 1) * 8;
    const int lbn = r >> 4, lbk = r & 15;
    const int lrow = (lbn >> 2)*512 + j0 + (lbn & 3);

    ull acc[4];
#pragma unroll
    for (int i = 0; i < 4; i++) acc[i] = fdup(0.f);

    float4 ra0, ra1; float rb;
    // tile 0 -> regs -> buf 0
    ra0 = *(const float4*)&g_u[lm*1024 + kbase + lkq];
    ra1 = *(const float4*)&g_u[lm*1024 + kbase + lkq + 4];
    rb  = g_wcat[(size_t)lrow*1024 + kbase + lbk];
    {
        float* a = As + (khb + lkq)*136 + lm;
        a[0]   = ra0.x; a[136] = ra0.y; a[272] = ra0.z; a[408] = ra0.w;
        a[544] = ra1.x; a[680] = ra1.y; a[816] = ra1.z; a[952] = ra1.w;
        Bsh[(khb + lbk)*16 + lbn] = rb;
    }
    // tile 1 -> regs
    ra0 = *(const float4*)&g_u[lm*1024 + kbase + 16 + lkq];
    ra1 = *(const float4*)&g_u[lm*1024 + kbase + 16 + lkq + 4];
    rb  = g_wcat[(size_t)lrow*1024 + kbase + 16 + lbk];
    __syncthreads();

    for (int it = 0; it < 32; it++){
        const int buf = it & 1;
        if (it + 1 < 32){
            float* a = As + (buf^1)*4352 + (khb + lkq)*136 + lm;
            a[0]   = ra0.x; a[136] = ra0.y; a[272] = ra0.z; a[408] = ra0.w;
            a[544] = ra1.x; a[680] = ra1.y; a[816] = ra1.z; a[952] = ra1.w;
            Bsh[(buf^1)*512 + (khb + lbk)*16 + lbn] = rb;
        }
        if (it + 2 < 32){
            int k0 = kbase + (it + 2)*16;
            ra0 = *(const float4*)&g_u[lm*1024 + k0 + lkq];
            ra1 = *(const float4*)&g_u[lm*1024 + k0 + lkq + 4];
            rb  = g_wcat[(size_t)lrow*1024 + k0 + lbk];
        }
        const float* Ab = As + buf*4352;
        const float* Bb = Bsh + buf*512;
#pragma unroll
        for (int kk = 0; kk < 16; kk++){
            ull b2 = fdup(Bb[(khb + kk)*16 + nn]);
            const ull* ap = (const ull*)(Ab + (khb + kk)*136 + 8*mg);
            fma2(acc[0], ap[0], b2);
            fma2(acc[1], ap[1], b2);
            fma2(acc[2], ap[2], b2);
            fma2(acc[3], ap[3], b2);
        }
        __syncthreads();
    }
    // reduce K-halves into ps[m][nn]
    if (kh == 1){
#pragma unroll
        for (int i = 0; i < 4; i++){
            float2 v = upk(acc[i]);
            ps[(8*mg + 2*i)*17 + nn]     = v.x;
            ps[(8*mg + 2*i + 1)*17 + nn] = v.y;
        }
    }
    __syncthreads();
    if (kh == 0){
#pragma unroll
        for (int i = 0; i < 4; i++){
            float2 v = upk(acc[i]);
            int m = 8*mg + 2*i;
            ps[m*17 + nn]     += v.x;
            ps[(m+1)*17 + nn] += v.y;
        }
    }
    __syncthreads();
    // LSTM cell: thread -> (m = tid&127, jj = tid>>7), j = j0+jj
    {
        const int me = tid & 127, jj = tid >> 7;
        const int j = j0 + jj;
        const float* xgb = g_xg + (size_t)t*BB*2048 + (size_t)me*2048;
        float ig = fsig (ps[me*17 + jj]      + xgb[j]);
        float fg = fsig (ps[me*17 + 4 + jj]  + xgb[512  + j]);
        float gg = ftanh(ps[me*17 + 8 + jj]  + xgb[1024 + j]);
        float og = fsig (ps[me*17 + 12 + jj] + xgb[1536 + j]);
        float cn = fmaf(fg, cr, ig*gg);
        cr = cn;
        g_u[me*1024 + 512 + j] = og * ftanh(cn);
    }
    __syncthreads();
}

// ------------------------- persistent decoder (2 barriers/step) --------------
__global__ void __launch_bounds__(512)
k_decoder(const float* __restrict__ attn_W, const float* __restrict__ attn_v,
          const float* __restrict__ out_W, const float* __restrict__ out_b,
          float* __restrict__ out)
{
    __shared__ __align__(16) float sm[11904];
    const int bid = blockIdx.x, tid = threadIdx.x;
    const int j0 = bid * 4;
    unsigned tgt = g_bar_epoch;

    float cr;
    {
        const int me = tid & 127, jj = tid >> 7;
        const int j = j0 + jj;
        float h;
        if (j < 256){ h = g_h_enc[0][0][me*256 + j];       cr = g_c_enc[0][me*256 + j]; }
        else        { h = g_h_enc[0][1][me*256 + j - 256]; cr = g_c_enc[1][me*256 + j - 256]; }
        g_u[me*1024 + 512 + j] = h;
    }
    tgt++; dbar(tgt);

    for (int t = 0; t < TT; t++){
        attention(sm, bid, t, attn_W, attn_v, out_W, out_b, out);
        tgt++; dbar(tgt);
        gmC(sm, j0, t, cr);
        tgt++; dbar(tgt);
    }
    // final logits -> out[:, 127, :]
    dec_logits(sm, bid, TT, out_W, out_b, out);
}

// ------------------------- launch --------------------------------------------
extern "C" void kernel_launch(void* const* d_in, const int* in_sizes, int n_in,
                              void* d_out, int out_size)
{
    const int*   src     = (const int*)  d_in[0];
    const int*   trg     = (const int*)  d_in[1];
    const float* enc_emb = (const float*)d_in[2];
    const float* Wih_f   = (const float*)d_in[3];
    const float* Whh_f   = (const float*)d_in[4];
    const float* b_f     = (const float*)d_in[5];
    const float* Wih_b   = (const float*)d_in[6];
    const float* Whh_b   = (const float*)d_in[7];
    const float* b_b     = (const float*)d_in[8];
    const float* dec_emb = (const float*)d_in[9];
    const float* dec_Wih = (const float*)d_in[10];
    const float* dec_Whh = (const float*)d_in[11];
    const float* dec_b   = (const float*)d_in[12];
    const float* attn_W  = (const float*)d_in[13];
    const float* attn_b  = (const float*)d_in[14];
    const float* attn_v  = (const float*)d_in[15];
    const float* out_W   = (const float*)d_in[16];
    const float* out_b   = (const float*)d_in[17];
    float* out = (float*)d_out;

    cudaFuncSetAttribute(k_encoder,
        cudaFuncAttributeMaxDynamicSharedMemorySize, 256*132*4);

    // 1) fused prep + input-gate GEMMs
    k_pre<<<dim3(32, 1024, 3), 256>>>(src, trg, enc_emb, dec_emb,
                                      Wih_f, b_f, Wih_b, b_b,
                                      dec_Wih, dec_Whh, dec_b, out);
    // 2) persistent encoder
    k_encoder<<<128, 256, 256*132*4>>>(Whh_f, Whh_b);
    // 3) enc_proj = enc_out(bf16) @ We + attn_b -> bf16
    sgemm_proj<<<dim3(512/64, (BB*SS)/64), 256>>>(attn_W + 512*512, attn_b);
    // 4) persistent decoder
    k_decoder<<<128, 512>>>(attn_W, attn_v, out_W, out_b, out);
}